// round 10
// baseline (speedup 1.0000x reference)
#include <cuda_runtime.h>
#include <cuda_bf16.h>
#include <math.h>
#include <stdint.h>

// Problem dims
#define BB 16
#define NN 512
#define DD 512
#define RR 8
#define TD (3*DD)

// ---------------------------------------------------------------------------
// Scratch (__device__ globals; allocation-free)
// ---------------------------------------------------------------------------
static __device__ __align__(256) float g_h[(size_t)BB*NN*DD];
static __device__ __align__(256) float g_gi[(size_t)BB*NN*TD];
static __device__ __align__(256) float g_gh[(size_t)BB*NN*TD];
static __device__ __align__(256) float g_bias_sum[DD];

static __device__ __align__(256) __nv_bfloat16 g_hhi[(size_t)BB*NN*DD];
static __device__ __align__(256) __nv_bfloat16 g_hlo[(size_t)BB*NN*DD];
static __device__ __align__(256) __nv_bfloat16 g_ehi[(size_t)BB*RR*NN*NN];
static __device__ __align__(256) __nv_bfloat16 g_elo[(size_t)BB*RR*NN*NN];
static __device__ __align__(256) __nv_bfloat16 g_Whi[(size_t)RR*DD*DD];
static __device__ __align__(256) __nv_bfloat16 g_Wlo[(size_t)RR*DD*DD];
static __device__ __align__(256) __nv_bfloat16 g_wihhi[(size_t)TD*DD];
static __device__ __align__(256) __nv_bfloat16 g_wihlo[(size_t)TD*DD];
static __device__ __align__(256) __nv_bfloat16 g_whhhi[(size_t)TD*DD];
static __device__ __align__(256) __nv_bfloat16 g_whhlo[(size_t)TD*DD];
static __device__ __align__(256) __nv_bfloat16 g_hWThi[(size_t)RR*DD*BB*NN]; // [r][e][j]
static __device__ __align__(256) __nv_bfloat16 g_hWTlo[(size_t)RR*DD*BB*NN];
static __device__ __align__(256) __nv_bfloat16 g_agghi[(size_t)BB*NN*DD];
static __device__ __align__(256) __nv_bfloat16 g_agglo[(size_t)BB*NN*DD];

// ---------------------------------------------------------------------------
// PTX helpers (all non-'a' ISA: cp.async / ldmatrix / mma.sync)
// ---------------------------------------------------------------------------
__device__ __forceinline__ uint32_t s2u(const void* p) {
  uint32_t a;
  asm("{ .reg .u64 t; cvta.to.shared.u64 t, %1; cvt.u32.u64 %0, t; }" : "=r"(a) : "l"(p));
  return a;
}
__device__ __forceinline__ void cp16(uint32_t s, const void* g) {
  asm volatile("cp.async.cg.shared.global [%0], [%1], 16;" :: "r"(s), "l"(g));
}
#define CP_COMMIT() asm volatile("cp.async.commit_group;" ::: "memory")

#define LDSM4(r, a) \
  asm volatile("ldmatrix.sync.aligned.m8n8.x4.shared.b16 {%0,%1,%2,%3},[%4];" \
    : "=r"((r)[0]),"=r"((r)[1]),"=r"((r)[2]),"=r"((r)[3]) : "r"(a))

#define MMA(d, a, b0, b1) \
  asm volatile("mma.sync.aligned.m16n8k16.row.col.f32.bf16.bf16.f32 " \
    "{%0,%1,%2,%3},{%4,%5,%6,%7},{%8,%9},{%0,%1,%2,%3};" \
    : "+f"((d)[0]),"+f"((d)[1]),"+f"((d)[2]),"+f"((d)[3]) \
    : "r"((a)[0]),"r"((a)[1]),"r"((a)[2]),"r"((a)[3]),"r"(b0),"r"(b1))

// ---------------------------------------------------------------------------
// GEMM core: CTA 128x128x32, 8 warps (4M x 2N), warp tile 32x64
// smem rows padded to 40 bf16 (80B) -> conflict-free ldmatrix phases
// 3-stage cp.async pipeline, single __syncthreads per K-iteration.
// Layout/stage: Ahi @0 (10240B) | Alo @10240 | Bhi @20480 | Blo @30720
// ---------------------------------------------------------------------------
#define STAGE_BYTES 40960
#define DYN_SMEM (3*STAGE_BYTES)
#define LDP 80   // padded row pitch in bytes (40 bf16)

struct TilePtrs { const __nv_bfloat16 *ah, *al, *bh, *bl; };

template <class F>
__device__ __forceinline__ void gemm_mma(F f, int niters, int lda, int ldb,
                                         float acc[2][8][4]) {
  extern __shared__ char smem[];
  const uint32_t sb = s2u(smem);
  const int tid = threadIdx.x;
  const int lane = tid & 31, w = tid >> 5;
  const int wm = w & 3, wn = w >> 2;

  #pragma unroll
  for (int a = 0; a < 2; ++a)
    #pragma unroll
    for (int b = 0; b < 8; ++b)
      #pragma unroll
      for (int c = 0; c < 4; ++c) acc[a][b][c] = 0.f;

  auto load_stage = [&](int s, int it) {
    TilePtrs p = f(it);
    uint32_t st = sb + (uint32_t)s * STAGE_BYTES;
    #pragma unroll
    for (int l = 0; l < 2; ++l) {
      int i = tid + l * 256;
      int r = i >> 2, c = i & 3;                 // r: 0..127 row, c: 16B chunk
      uint32_t o = (uint32_t)r * LDP + c * 16;
      cp16(st + o,         p.ah + (size_t)r * lda + c * 8);
      cp16(st + 10240 + o, p.al + (size_t)r * lda + c * 8);
      cp16(st + 20480 + o, p.bh + (size_t)r * ldb + c * 8);
      cp16(st + 30720 + o, p.bl + (size_t)r * ldb + c * 8);
    }
    CP_COMMIT();
  };

  // ldmatrix lane address offsets
  const uint32_t aLane = (uint32_t)(lane & 15) * LDP + (lane >> 4) * 16;
  const uint32_t bLane = (uint32_t)((lane & 7) + ((lane >> 4) << 3)) * LDP
                       + ((lane >> 3) & 1) * 16;

  load_stage(0, 0);
  if (niters > 1) load_stage(1, 1);

  int stage = 0;
  for (int it = 0; it < niters; ++it) {
    if (it + 1 < niters)
      asm volatile("cp.async.wait_group 1;" ::: "memory");
    else
      asm volatile("cp.async.wait_group 0;" ::: "memory");
    __syncthreads();
    if (it + 2 < niters) {
      int ns = stage + 2; if (ns >= 3) ns -= 3;
      load_stage(ns, it + 2);
    }
    uint32_t st = sb + (uint32_t)stage * STAGE_BYTES;
    uint32_t aBase = st + (uint32_t)(wm * 32) * LDP + aLane;
    uint32_t bBase = st + 20480 + (uint32_t)(wn * 64) * LDP + bLane;
    #pragma unroll
    for (int k16 = 0; k16 < 2; ++k16) {
      uint32_t ah[2][4], al[2][4], bh[4][4], bl[4][4];
      #pragma unroll
      for (int mt = 0; mt < 2; ++mt) {
        uint32_t a = aBase + (uint32_t)(mt * 16) * LDP + k16 * 32;
        LDSM4(ah[mt], a);
        LDSM4(al[mt], a + 10240);
      }
      #pragma unroll
      for (int g = 0; g < 4; ++g) {
        uint32_t b = bBase + (uint32_t)(g * 16) * LDP + k16 * 32;
        LDSM4(bh[g], b);
        LDSM4(bl[g], b + 10240);
      }
      // Product-outermost order: 16 independent accumulators between any
      // reuse of the same acc tile -> HMMA latency fully hidden.
      #pragma unroll
      for (int prod = 0; prod < 3; ++prod) {
        #pragma unroll
        for (int mt = 0; mt < 2; ++mt)
          #pragma unroll
          for (int g = 0; g < 4; ++g)
            #pragma unroll
            for (int t = 0; t < 2; ++t) {
              float* d = acc[mt][g * 2 + t];
              const uint32_t* A = (prod == 2) ? al[mt] : ah[mt];
              const uint32_t (&B)[4] = (prod == 1) ? bl[g] : bh[g];
              MMA(d, A, B[2*t], B[2*t+1]);
            }
      }
    }
    ++stage; if (stage >= 3) stage -= 3;
  }
}

// Epilogue index helpers: element (row,col) of acc[mt][nt][cr]
//   row = row0 + wm*32 + mt*16 + (lane>>2) + ((cr>>1)<<3)
//   col = col0 + wn*64 + nt*8 + (lane&3)*2 + (cr&1)

// ---------------------------------------------------------------------------
// K1: hWT[r][e][j] = sum_d h[j,d] * W[r][e,d]; writes transposed + split
// grid (64, 4, 8)
// ---------------------------------------------------------------------------
__global__ void __launch_bounds__(256) k_hw_t() {
  const int row0 = blockIdx.x * 128, col0 = blockIdx.y * 128, r = blockIdx.z;
  auto f = [&](int it) -> TilePtrs {
    int k0 = it * 32;
    TilePtrs p;
    p.ah = g_hhi + (size_t)row0 * DD + k0;
    p.al = g_hlo + (size_t)row0 * DD + k0;
    p.bh = g_Whi + ((size_t)r * DD + col0) * DD + k0;
    p.bl = g_Wlo + ((size_t)r * DD + col0) * DD + k0;
    return p;
  };
  float acc[2][8][4];
  gemm_mma(f, 16, DD, DD, acc);
  const int lane = threadIdx.x & 31, w = threadIdx.x >> 5;
  const int wm = w & 3, wn = w >> 2, grp = lane >> 2, tig = lane & 3;
  #pragma unroll
  for (int mt = 0; mt < 2; ++mt)
    #pragma unroll
    for (int nt = 0; nt < 8; ++nt)
      #pragma unroll
      for (int cr = 0; cr < 4; ++cr) {
        int j = row0 + wm * 32 + mt * 16 + grp + ((cr >> 1) << 3);
        int e = col0 + wn * 64 + nt * 8 + tig * 2 + (cr & 1);
        float v = acc[mt][nt][cr];
        size_t o = ((size_t)r * DD + e) * (size_t)(BB * NN) + j;
        __nv_bfloat16 hh = __float2bfloat16(v);
        g_hWThi[o] = hh;
        g_hWTlo[o] = __float2bfloat16(v - __bfloat162float(hh));
      }
}

// ---------------------------------------------------------------------------
// K2: agg[b][i][e] = sum_r sum_j edges[b,r,i,j]*hWT[r][e][b*512+j] + bias_sum
// grid (4, 4, 16); niters = 8 r * 16 k-chunks = 128
// ---------------------------------------------------------------------------
__global__ void __launch_bounds__(256) k_agg_t() {
  const int b = blockIdx.z, row0 = blockIdx.x * 128, col0 = blockIdx.y * 128;
  auto f = [&](int it) -> TilePtrs {
    int r = it >> 4, k0 = (it & 15) * 32;
    TilePtrs p;
    size_t ea = ((size_t)(b * RR + r) * NN + row0) * NN + k0;
    size_t wb = ((size_t)r * DD + col0) * (size_t)(BB * NN) + (size_t)b * NN + k0;
    p.ah = g_ehi + ea;   p.al = g_elo + ea;
    p.bh = g_hWThi + wb; p.bl = g_hWTlo + wb;
    return p;
  };
  float acc[2][8][4];
  gemm_mma(f, 128, NN, BB * NN, acc);
  const int lane = threadIdx.x & 31, w = threadIdx.x >> 5;
  const int wm = w & 3, wn = w >> 2, grp = lane >> 2, tig = lane & 3;
  #pragma unroll
  for (int mt = 0; mt < 2; ++mt)
    #pragma unroll
    for (int nt = 0; nt < 8; ++nt)
      #pragma unroll
      for (int cr = 0; cr < 4; ++cr) {
        int i = row0 + wm * 32 + mt * 16 + grp + ((cr >> 1) << 3);
        int e = col0 + wn * 64 + nt * 8 + tig * 2 + (cr & 1);
        float v = acc[mt][nt][cr] + g_bias_sum[e];
        size_t o = (size_t)(b * NN + i) * DD + e;
        __nv_bfloat16 hh = __float2bfloat16(v);
        g_agghi[o] = hh;
        g_agglo[o] = __float2bfloat16(v - __bfloat162float(hh));
      }
}

// ---------------------------------------------------------------------------
// K3: gates C[8192,1536] = A @ W^T + bias (fp32 out)
// a_sel: 0 -> agg splits, 1 -> h splits; out_sel: 0 -> g_gi, 1 -> g_gh
// grid (64, 12)
// ---------------------------------------------------------------------------
__global__ void __launch_bounds__(256) k_gates_t(int a_sel, int w_sel,
                                                 const float* __restrict__ bias,
                                                 int out_sel) {
  const int row0 = blockIdx.x * 128, col0 = blockIdx.y * 128;
  const __nv_bfloat16* Ah = a_sel ? g_hhi : g_agghi;
  const __nv_bfloat16* Al = a_sel ? g_hlo : g_agglo;
  const __nv_bfloat16* Wh = w_sel ? g_whhhi : g_wihhi;
  const __nv_bfloat16* Wl = w_sel ? g_whhlo : g_wihlo;
  float* C = out_sel ? g_gh : g_gi;
  auto f = [&](int it) -> TilePtrs {
    int k0 = it * 32;
    TilePtrs p;
    p.ah = Ah + (size_t)row0 * DD + k0;
    p.al = Al + (size_t)row0 * DD + k0;
    p.bh = Wh + (size_t)col0 * DD + k0;
    p.bl = Wl + (size_t)col0 * DD + k0;
    return p;
  };
  float acc[2][8][4];
  gemm_mma(f, 16, DD, DD, acc);
  const int lane = threadIdx.x & 31, w = threadIdx.x >> 5;
  const int wm = w & 3, wn = w >> 2, grp = lane >> 2, tig = lane & 3;
  #pragma unroll
  for (int mt = 0; mt < 2; ++mt)
    #pragma unroll
    for (int nt = 0; nt < 8; ++nt)
      #pragma unroll
      for (int cr = 0; cr < 4; ++cr) {
        int row = row0 + wm * 32 + mt * 16 + grp + ((cr >> 1) << 3);
        int e = col0 + wn * 64 + nt * 8 + tig * 2 + (cr & 1);
        C[(size_t)row * TD + e] = acc[mt][nt][cr] + bias[e];
      }
}

// ---------------------------------------------------------------------------
// Split & misc kernels
// ---------------------------------------------------------------------------
__global__ void k_split(const float4* __restrict__ s, __nv_bfloat162* __restrict__ hi,
                        __nv_bfloat162* __restrict__ lo, int n4) {
  int i = blockIdx.x * blockDim.x + threadIdx.x;
  if (i >= n4) return;
  float4 v = s[i];
  __nv_bfloat16 hx = __float2bfloat16(v.x), hy = __float2bfloat16(v.y);
  __nv_bfloat16 hz = __float2bfloat16(v.z), hw = __float2bfloat16(v.w);
  __nv_bfloat162 h0; h0.x = hx; h0.y = hy;
  __nv_bfloat162 h1; h1.x = hz; h1.y = hw;
  __nv_bfloat162 l0; l0.x = __float2bfloat16(v.x - __bfloat162float(hx));
                     l0.y = __float2bfloat16(v.y - __bfloat162float(hy));
  __nv_bfloat162 l1; l1.x = __float2bfloat16(v.z - __bfloat162float(hz));
                     l1.y = __float2bfloat16(v.w - __bfloat162float(hw));
  hi[2*i] = h0; hi[2*i+1] = h1;
  lo[2*i] = l0; lo[2*i+1] = l1;
}

__global__ void k_bias(const float* __restrict__ mb) {
  int d = threadIdx.x;
  float s = 0.f;
  #pragma unroll
  for (int r = 0; r < RR; ++r) s += mb[r * DD + d];
  g_bias_sum[d] = s;
}

__global__ void k_gru(const float* __restrict__ nodes, int step) {
  int idx = blockIdx.x * blockDim.x + threadIdx.x;
  const float* hsrc = (step == 0) ? nodes : g_h;
  int d = idx & (DD - 1);
  int row = idx >> 9;
  const float* gi = g_gi + (size_t)row * TD;
  const float* gh = g_gh + (size_t)row * TD;
  float ir = gi[d],        hr = gh[d];
  float iz = gi[DD + d],   hz = gh[DD + d];
  float in_ = gi[2*DD + d], hn = gh[2*DD + d];
  float r = 1.f / (1.f + expf(-(ir + hr)));
  float z = 1.f / (1.f + expf(-(iz + hz)));
  float n = tanhf(in_ + r * hn);
  float h = hsrc[idx];
  float hnew = (1.f - z) * n + z * h;
  g_h[idx] = hnew;
  __nv_bfloat16 hh = __float2bfloat16(hnew);
  g_hhi[idx] = hh;
  g_hlo[idx] = __float2bfloat16(hnew - __bfloat162float(hh));
}

__global__ void k_mean(float* __restrict__ out) {
  int b = blockIdx.x, d = threadIdx.x;
  const float* hp = g_h + (size_t)b * NN * DD + d;
  float s = 0.f;
  for (int i = 0; i < NN; ++i) s += hp[(size_t)i * DD];
  out[b * DD + d] = s * (1.0f / NN);
}

// ---------------------------------------------------------------------------
extern "C" void kernel_launch(void* const* d_in, const int* in_sizes, int n_in,
                              void* d_out, int out_size) {
  const float* nodes = (const float*)d_in[0];
  const float* edges = (const float*)d_in[1];
  const float* msg_W = (const float*)d_in[2];
  const float* msg_b = (const float*)d_in[3];
  const float* b_ih  = (const float*)d_in[6];
  const float* b_hh  = (const float*)d_in[7];
  float* out = (float*)d_out;

  cudaFuncSetAttribute(k_hw_t,    cudaFuncAttributeMaxDynamicSharedMemorySize, DYN_SMEM);
  cudaFuncSetAttribute(k_agg_t,   cudaFuncAttributeMaxDynamicSharedMemorySize, DYN_SMEM);
  cudaFuncSetAttribute(k_gates_t, cudaFuncAttributeMaxDynamicSharedMemorySize, DYN_SMEM);

  __nv_bfloat162 *hhi2, *hlo2, *ehi2, *elo2, *whi2, *wlo2, *ihhi2, *ihlo2, *hhhi2, *hhlo2;
  cudaGetSymbolAddress((void**)&hhi2,  g_hhi);   cudaGetSymbolAddress((void**)&hlo2,  g_hlo);
  cudaGetSymbolAddress((void**)&ehi2,  g_ehi);   cudaGetSymbolAddress((void**)&elo2,  g_elo);
  cudaGetSymbolAddress((void**)&whi2,  g_Whi);   cudaGetSymbolAddress((void**)&wlo2,  g_Wlo);
  cudaGetSymbolAddress((void**)&ihhi2, g_wihhi); cudaGetSymbolAddress((void**)&ihlo2, g_wihlo);
  cudaGetSymbolAddress((void**)&hhhi2, g_whhhi); cudaGetSymbolAddress((void**)&hhlo2, g_whhlo);

  int n4;
  n4 = BB*NN*DD/4;    k_split<<<n4/256, 256>>>((const float4*)nodes, hhi2, hlo2, n4);
  n4 = BB*RR*NN*NN/4; k_split<<<n4/256, 256>>>((const float4*)edges, ehi2, elo2, n4);
  n4 = RR*DD*DD/4;    k_split<<<n4/256, 256>>>((const float4*)msg_W, whi2, wlo2, n4);
  n4 = TD*DD/4;       k_split<<<n4/256, 256>>>((const float4*)d_in[4], ihhi2, ihlo2, n4);
  n4 = TD*DD/4;       k_split<<<n4/256, 256>>>((const float4*)d_in[5], hhhi2, hhlo2, n4);
  k_bias<<<1, DD>>>(msg_b);

  for (int s = 0; s < 2; ++s) {
    k_hw_t   <<<dim3(64, 4, 8),  256, DYN_SMEM>>>();
    k_agg_t  <<<dim3(4, 4, 16),  256, DYN_SMEM>>>();
    k_gates_t<<<dim3(64, 12),    256, DYN_SMEM>>>(0, 0, b_ih, 0);
    k_gates_t<<<dim3(64, 12),    256, DYN_SMEM>>>(1, 1, b_hh, 1);
    k_gru    <<<(BB*NN*DD)/256, 256>>>(nodes, s);
  }
  k_mean<<<BB, DD>>>(out);
}

// round 11
// speedup vs baseline: 1.1523x; 1.1523x over previous
#include <cuda_runtime.h>
#include <cuda_bf16.h>
#include <math.h>
#include <stdint.h>

// Problem dims
#define BB 16
#define NN 512
#define DD 512
#define RR 8
#define TD (3*DD)

// ---------------------------------------------------------------------------
// Scratch (__device__ globals; allocation-free)
// ---------------------------------------------------------------------------
static __device__ __align__(256) float g_h[(size_t)BB*NN*DD];
static __device__ __align__(256) float g_gi[(size_t)BB*NN*TD];
static __device__ __align__(256) float g_gh[(size_t)BB*NN*TD];
static __device__ __align__(256) float g_bias_sum[DD];

static __device__ __align__(256) __nv_bfloat16 g_hhi[(size_t)BB*NN*DD];
static __device__ __align__(256) __nv_bfloat16 g_hlo[(size_t)BB*NN*DD];
static __device__ __align__(256) __nv_bfloat16 g_ehi[(size_t)BB*RR*NN*NN];
static __device__ __align__(256) __nv_bfloat16 g_elo[(size_t)BB*RR*NN*NN];
static __device__ __align__(256) __nv_bfloat16 g_Whi[(size_t)RR*DD*DD];
static __device__ __align__(256) __nv_bfloat16 g_Wlo[(size_t)RR*DD*DD];
static __device__ __align__(256) __nv_bfloat16 g_wihhi[(size_t)TD*DD];
static __device__ __align__(256) __nv_bfloat16 g_wihlo[(size_t)TD*DD];
static __device__ __align__(256) __nv_bfloat16 g_whhhi[(size_t)TD*DD];
static __device__ __align__(256) __nv_bfloat16 g_whhlo[(size_t)TD*DD];
static __device__ __align__(256) __nv_bfloat16 g_hWThi[(size_t)RR*DD*BB*NN]; // [r][e][j]
static __device__ __align__(256) __nv_bfloat16 g_hWTlo[(size_t)RR*DD*BB*NN];
static __device__ __align__(256) __nv_bfloat16 g_agghi[(size_t)BB*NN*DD];
static __device__ __align__(256) __nv_bfloat16 g_agglo[(size_t)BB*NN*DD];

// ---------------------------------------------------------------------------
// PTX helpers (all non-'a' ISA: cp.async / ldmatrix / mma.sync)
// ---------------------------------------------------------------------------
__device__ __forceinline__ uint32_t s2u(const void* p) {
  uint32_t a;
  asm("{ .reg .u64 t; cvta.to.shared.u64 t, %1; cvt.u32.u64 %0, t; }" : "=r"(a) : "l"(p));
  return a;
}
__device__ __forceinline__ void cp16(uint32_t s, const void* g) {
  asm volatile("cp.async.cg.shared.global [%0], [%1], 16;" :: "r"(s), "l"(g));
}
#define CP_COMMIT() asm volatile("cp.async.commit_group;" ::: "memory")

#define LDSM4(r, a) \
  asm volatile("ldmatrix.sync.aligned.m8n8.x4.shared.b16 {%0,%1,%2,%3},[%4];" \
    : "=r"((r)[0]),"=r"((r)[1]),"=r"((r)[2]),"=r"((r)[3]) : "r"(a))

#define MMA(d, a, b0, b1) \
  asm volatile("mma.sync.aligned.m16n8k16.row.col.f32.bf16.bf16.f32 " \
    "{%0,%1,%2,%3},{%4,%5,%6,%7},{%8,%9},{%0,%1,%2,%3};" \
    : "+f"((d)[0]),"+f"((d)[1]),"+f"((d)[2]),"+f"((d)[3]) \
    : "r"((a)[0]),"r"((a)[1]),"r"((a)[2]),"r"((a)[3]),"r"(b0),"r"(b1))

// ---------------------------------------------------------------------------
// GEMM core: CTA 128x128x32, 8 warps (4M x 2N), warp tile 32x64
// smem rows padded to 40 bf16 (80B) -> conflict-free ldmatrix phases
// 2-stage cp.async pipeline (80KB -> 2 CTAs/SM), product-outermost MMA order.
// Layout/stage: Ahi @0 (10240B) | Alo @10240 | Bhi @20480 | Blo @30720
// ---------------------------------------------------------------------------
#define STAGE_BYTES 40960
#define DYN_SMEM (2*STAGE_BYTES)
#define LDP 80   // padded row pitch in bytes (40 bf16)

struct TilePtrs { const __nv_bfloat16 *ah, *al, *bh, *bl; };

template <class F>
__device__ __forceinline__ void gemm_mma(F f, int niters, int lda, int ldb,
                                         float acc[2][8][4]) {
  extern __shared__ char smem[];
  const uint32_t sb = s2u(smem);
  const int tid = threadIdx.x;
  const int lane = tid & 31, w = tid >> 5;
  const int wm = w & 3, wn = w >> 2;

  #pragma unroll
  for (int a = 0; a < 2; ++a)
    #pragma unroll
    for (int b = 0; b < 8; ++b)
      #pragma unroll
      for (int c = 0; c < 4; ++c) acc[a][b][c] = 0.f;

  auto load_stage = [&](int s, int it) {
    TilePtrs p = f(it);
    uint32_t st = sb + (uint32_t)s * STAGE_BYTES;
    #pragma unroll
    for (int l = 0; l < 2; ++l) {
      int i = tid + l * 256;
      int r = i >> 2, c = i & 3;                 // r: 0..127 row, c: 16B chunk
      uint32_t o = (uint32_t)r * LDP + c * 16;
      cp16(st + o,         p.ah + (size_t)r * lda + c * 8);
      cp16(st + 10240 + o, p.al + (size_t)r * lda + c * 8);
      cp16(st + 20480 + o, p.bh + (size_t)r * ldb + c * 8);
      cp16(st + 30720 + o, p.bl + (size_t)r * ldb + c * 8);
    }
    CP_COMMIT();
  };

  // ldmatrix lane address offsets
  const uint32_t aLane = (uint32_t)(lane & 15) * LDP + (lane >> 4) * 16;
  const uint32_t bLane = (uint32_t)((lane & 7) + ((lane >> 4) << 3)) * LDP
                       + ((lane >> 3) & 1) * 16;

  load_stage(0, 0);
  for (int it = 0; it < niters; ++it) {
    if (it + 1 < niters) {
      load_stage((it + 1) & 1, it + 1);
      asm volatile("cp.async.wait_group 1;" ::: "memory");
    } else {
      asm volatile("cp.async.wait_group 0;" ::: "memory");
    }
    __syncthreads();
    uint32_t st = sb + (uint32_t)((it & 1)) * STAGE_BYTES;
    uint32_t aBase = st + (uint32_t)(wm * 32) * LDP + aLane;
    uint32_t bBase = st + 20480 + (uint32_t)(wn * 64) * LDP + bLane;
    #pragma unroll
    for (int k16 = 0; k16 < 2; ++k16) {
      uint32_t ah[2][4], al[2][4], bh[4][4], bl[4][4];
      #pragma unroll
      for (int mt = 0; mt < 2; ++mt) {
        uint32_t a = aBase + (uint32_t)(mt * 16) * LDP + k16 * 32;
        LDSM4(ah[mt], a);
        LDSM4(al[mt], a + 10240);
      }
      #pragma unroll
      for (int g = 0; g < 4; ++g) {
        uint32_t b = bBase + (uint32_t)(g * 16) * LDP + k16 * 32;
        LDSM4(bh[g], b);
        LDSM4(bl[g], b + 10240);
      }
      // Product-outermost: 16 independent accumulators between any reuse of
      // the same acc tile -> HMMA latency hidden within a single warp.
      #pragma unroll
      for (int prod = 0; prod < 3; ++prod) {
        #pragma unroll
        for (int mt = 0; mt < 2; ++mt)
          #pragma unroll
          for (int g = 0; g < 4; ++g)
            #pragma unroll
            for (int t = 0; t < 2; ++t) {
              float* d = acc[mt][g * 2 + t];
              const uint32_t* A = (prod == 2) ? al[mt] : ah[mt];
              const uint32_t (&B)[4] = (prod == 1) ? bl[g] : bh[g];
              MMA(d, A, B[2*t], B[2*t+1]);
            }
      }
    }
    __syncthreads();
  }
}

// Epilogue index helpers: element (row,col) of acc[mt][nt][cr]
//   row = row0 + wm*32 + mt*16 + (lane>>2) + ((cr>>1)<<3)
//   col = col0 + wn*64 + nt*8 + (lane&3)*2 + (cr&1)

// ---------------------------------------------------------------------------
// K1: hWT[r][e][j] = sum_d h[j,d] * W[r][e,d]; writes transposed + split
// grid (64, 4, 8)
// ---------------------------------------------------------------------------
__global__ void __launch_bounds__(256, 2) k_hw_t() {
  const int row0 = blockIdx.x * 128, col0 = blockIdx.y * 128, r = blockIdx.z;
  auto f = [&](int it) -> TilePtrs {
    int k0 = it * 32;
    TilePtrs p;
    p.ah = g_hhi + (size_t)row0 * DD + k0;
    p.al = g_hlo + (size_t)row0 * DD + k0;
    p.bh = g_Whi + ((size_t)r * DD + col0) * DD + k0;
    p.bl = g_Wlo + ((size_t)r * DD + col0) * DD + k0;
    return p;
  };
  float acc[2][8][4];
  gemm_mma(f, 16, DD, DD, acc);
  const int lane = threadIdx.x & 31, w = threadIdx.x >> 5;
  const int wm = w & 3, wn = w >> 2, grp = lane >> 2, tig = lane & 3;
  #pragma unroll
  for (int mt = 0; mt < 2; ++mt)
    #pragma unroll
    for (int nt = 0; nt < 8; ++nt)
      #pragma unroll
      for (int cr = 0; cr < 4; ++cr) {
        int j = row0 + wm * 32 + mt * 16 + grp + ((cr >> 1) << 3);
        int e = col0 + wn * 64 + nt * 8 + tig * 2 + (cr & 1);
        float v = acc[mt][nt][cr];
        size_t o = ((size_t)r * DD + e) * (size_t)(BB * NN) + j;
        __nv_bfloat16 hh = __float2bfloat16(v);
        g_hWThi[o] = hh;
        g_hWTlo[o] = __float2bfloat16(v - __bfloat162float(hh));
      }
}

// ---------------------------------------------------------------------------
// K2: agg[b][i][e] = sum_r sum_j edges[b,r,i,j]*hWT[r][e][b*512+j] + bias_sum
// grid (4, 4, 16); niters = 8 r * 16 k-chunks = 128
// ---------------------------------------------------------------------------
__global__ void __launch_bounds__(256, 2) k_agg_t() {
  const int b = blockIdx.z, row0 = blockIdx.x * 128, col0 = blockIdx.y * 128;
  auto f = [&](int it) -> TilePtrs {
    int r = it >> 4, k0 = (it & 15) * 32;
    TilePtrs p;
    size_t ea = ((size_t)(b * RR + r) * NN + row0) * NN + k0;
    size_t wb = ((size_t)r * DD + col0) * (size_t)(BB * NN) + (size_t)b * NN + k0;
    p.ah = g_ehi + ea;   p.al = g_elo + ea;
    p.bh = g_hWThi + wb; p.bl = g_hWTlo + wb;
    return p;
  };
  float acc[2][8][4];
  gemm_mma(f, 128, NN, BB * NN, acc);
  const int lane = threadIdx.x & 31, w = threadIdx.x >> 5;
  const int wm = w & 3, wn = w >> 2, grp = lane >> 2, tig = lane & 3;
  #pragma unroll
  for (int mt = 0; mt < 2; ++mt)
    #pragma unroll
    for (int nt = 0; nt < 8; ++nt)
      #pragma unroll
      for (int cr = 0; cr < 4; ++cr) {
        int i = row0 + wm * 32 + mt * 16 + grp + ((cr >> 1) << 3);
        int e = col0 + wn * 64 + nt * 8 + tig * 2 + (cr & 1);
        float v = acc[mt][nt][cr] + g_bias_sum[e];
        size_t o = (size_t)(b * NN + i) * DD + e;
        __nv_bfloat16 hh = __float2bfloat16(v);
        g_agghi[o] = hh;
        g_agglo[o] = __float2bfloat16(v - __bfloat162float(hh));
      }
}

// ---------------------------------------------------------------------------
// K3: gates C[8192,1536] = A @ W^T + bias (fp32 out)
// a_sel: 0 -> agg splits, 1 -> h splits; out_sel: 0 -> g_gi, 1 -> g_gh
// grid (64, 12)
// ---------------------------------------------------------------------------
__global__ void __launch_bounds__(256, 2) k_gates_t(int a_sel, int w_sel,
                                                    const float* __restrict__ bias,
                                                    int out_sel) {
  const int row0 = blockIdx.x * 128, col0 = blockIdx.y * 128;
  const __nv_bfloat16* Ah = a_sel ? g_hhi : g_agghi;
  const __nv_bfloat16* Al = a_sel ? g_hlo : g_agglo;
  const __nv_bfloat16* Wh = w_sel ? g_whhhi : g_wihhi;
  const __nv_bfloat16* Wl = w_sel ? g_whhlo : g_wihlo;
  float* C = out_sel ? g_gh : g_gi;
  auto f = [&](int it) -> TilePtrs {
    int k0 = it * 32;
    TilePtrs p;
    p.ah = Ah + (size_t)row0 * DD + k0;
    p.al = Al + (size_t)row0 * DD + k0;
    p.bh = Wh + (size_t)col0 * DD + k0;
    p.bl = Wl + (size_t)col0 * DD + k0;
    return p;
  };
  float acc[2][8][4];
  gemm_mma(f, 16, DD, DD, acc);
  const int lane = threadIdx.x & 31, w = threadIdx.x >> 5;
  const int wm = w & 3, wn = w >> 2, grp = lane >> 2, tig = lane & 3;
  #pragma unroll
  for (int mt = 0; mt < 2; ++mt)
    #pragma unroll
    for (int nt = 0; nt < 8; ++nt)
      #pragma unroll
      for (int cr = 0; cr < 4; ++cr) {
        int row = row0 + wm * 32 + mt * 16 + grp + ((cr >> 1) << 3);
        int e = col0 + wn * 64 + nt * 8 + tig * 2 + (cr & 1);
        C[(size_t)row * TD + e] = acc[mt][nt][cr] + bias[e];
      }
}

// ---------------------------------------------------------------------------
// Split & misc kernels
// ---------------------------------------------------------------------------
__global__ void k_split(const float4* __restrict__ s, __nv_bfloat162* __restrict__ hi,
                        __nv_bfloat162* __restrict__ lo, int n4) {
  int i = blockIdx.x * blockDim.x + threadIdx.x;
  if (i >= n4) return;
  float4 v = s[i];
  __nv_bfloat16 hx = __float2bfloat16(v.x), hy = __float2bfloat16(v.y);
  __nv_bfloat16 hz = __float2bfloat16(v.z), hw = __float2bfloat16(v.w);
  __nv_bfloat162 h0; h0.x = hx; h0.y = hy;
  __nv_bfloat162 h1; h1.x = hz; h1.y = hw;
  __nv_bfloat162 l0; l0.x = __float2bfloat16(v.x - __bfloat162float(hx));
                     l0.y = __float2bfloat16(v.y - __bfloat162float(hy));
  __nv_bfloat162 l1; l1.x = __float2bfloat16(v.z - __bfloat162float(hz));
                     l1.y = __float2bfloat16(v.w - __bfloat162float(hw));
  hi[2*i] = h0; hi[2*i+1] = h1;
  lo[2*i] = l0; lo[2*i+1] = l1;
}

__global__ void k_bias(const float* __restrict__ mb) {
  int d = threadIdx.x;
  float s = 0.f;
  #pragma unroll
  for (int r = 0; r < RR; ++r) s += mb[r * DD + d];
  g_bias_sum[d] = s;
}

__global__ void k_gru(const float* __restrict__ nodes, int step) {
  int idx = blockIdx.x * blockDim.x + threadIdx.x;
  const float* hsrc = (step == 0) ? nodes : g_h;
  int d = idx & (DD - 1);
  int row = idx >> 9;
  const float* gi = g_gi + (size_t)row * TD;
  const float* gh = g_gh + (size_t)row * TD;
  float ir = gi[d],        hr = gh[d];
  float iz = gi[DD + d],   hz = gh[DD + d];
  float in_ = gi[2*DD + d], hn = gh[2*DD + d];
  float r = 1.f / (1.f + expf(-(ir + hr)));
  float z = 1.f / (1.f + expf(-(iz + hz)));
  float n = tanhf(in_ + r * hn);
  float h = hsrc[idx];
  float hnew = (1.f - z) * n + z * h;
  g_h[idx] = hnew;
  __nv_bfloat16 hh = __float2bfloat16(hnew);
  g_hhi[idx] = hh;
  g_hlo[idx] = __float2bfloat16(hnew - __bfloat162float(hh));
}

__global__ void k_mean(float* __restrict__ out) {
  int b = blockIdx.x, d = threadIdx.x;
  const float* hp = g_h + (size_t)b * NN * DD + d;
  float s = 0.f;
  for (int i = 0; i < NN; ++i) s += hp[(size_t)i * DD];
  out[b * DD + d] = s * (1.0f / NN);
}

// ---------------------------------------------------------------------------
extern "C" void kernel_launch(void* const* d_in, const int* in_sizes, int n_in,
                              void* d_out, int out_size) {
  const float* nodes = (const float*)d_in[0];
  const float* edges = (const float*)d_in[1];
  const float* msg_W = (const float*)d_in[2];
  const float* msg_b = (const float*)d_in[3];
  const float* b_ih  = (const float*)d_in[6];
  const float* b_hh  = (const float*)d_in[7];
  float* out = (float*)d_out;

  cudaFuncSetAttribute(k_hw_t,    cudaFuncAttributeMaxDynamicSharedMemorySize, DYN_SMEM);
  cudaFuncSetAttribute(k_agg_t,   cudaFuncAttributeMaxDynamicSharedMemorySize, DYN_SMEM);
  cudaFuncSetAttribute(k_gates_t, cudaFuncAttributeMaxDynamicSharedMemorySize, DYN_SMEM);

  __nv_bfloat162 *hhi2, *hlo2, *ehi2, *elo2, *whi2, *wlo2, *ihhi2, *ihlo2, *hhhi2, *hhlo2;
  cudaGetSymbolAddress((void**)&hhi2,  g_hhi);   cudaGetSymbolAddress((void**)&hlo2,  g_hlo);
  cudaGetSymbolAddress((void**)&ehi2,  g_ehi);   cudaGetSymbolAddress((void**)&elo2,  g_elo);
  cudaGetSymbolAddress((void**)&whi2,  g_Whi);   cudaGetSymbolAddress((void**)&wlo2,  g_Wlo);
  cudaGetSymbolAddress((void**)&ihhi2, g_wihhi); cudaGetSymbolAddress((void**)&ihlo2, g_wihlo);
  cudaGetSymbolAddress((void**)&hhhi2, g_whhhi); cudaGetSymbolAddress((void**)&hhlo2, g_whhlo);

  int n4;
  n4 = BB*NN*DD/4;    k_split<<<n4/256, 256>>>((const float4*)nodes, hhi2, hlo2, n4);
  n4 = BB*RR*NN*NN/4; k_split<<<n4/256, 256>>>((const float4*)edges, ehi2, elo2, n4);
  n4 = RR*DD*DD/4;    k_split<<<n4/256, 256>>>((const float4*)msg_W, whi2, wlo2, n4);
  n4 = TD*DD/4;       k_split<<<n4/256, 256>>>((const float4*)d_in[4], ihhi2, ihlo2, n4);
  n4 = TD*DD/4;       k_split<<<n4/256, 256>>>((const float4*)d_in[5], hhhi2, hhlo2, n4);
  k_bias<<<1, DD>>>(msg_b);

  for (int s = 0; s < 2; ++s) {
    k_hw_t   <<<dim3(64, 4, 8),  256, DYN_SMEM>>>();
    k_agg_t  <<<dim3(4, 4, 16),  256, DYN_SMEM>>>();
    k_gates_t<<<dim3(64, 12),    256, DYN_SMEM>>>(0, 0, b_ih, 0);
    k_gates_t<<<dim3(64, 12),    256, DYN_SMEM>>>(1, 1, b_hh, 1);
    k_gru    <<<(BB*NN*DD)/256, 256>>>(nodes, s);
  }
  k_mean<<<BB, DD>>>(out);
}

// round 12
// speedup vs baseline: 1.2040x; 1.0449x over previous
#include <cuda_runtime.h>
#include <cuda_bf16.h>
#include <math.h>
#include <stdint.h>

// Problem dims
#define BB 16
#define NN 512
#define DD 512
#define RR 8
#define TD (3*DD)

// ---------------------------------------------------------------------------
// Scratch (__device__ globals; allocation-free)
// ---------------------------------------------------------------------------
static __device__ __align__(256) float g_h[(size_t)BB*NN*DD];
static __device__ __align__(256) float g_gi[(size_t)BB*NN*TD];
static __device__ __align__(256) float g_gh[(size_t)BB*NN*TD];
static __device__ __align__(256) float g_bias_sum[DD];
static __device__ __align__(256) float g_msum[(size_t)BB*8*DD];

static __device__ __align__(256) __nv_bfloat16 g_hhi[(size_t)BB*NN*DD];
static __device__ __align__(256) __nv_bfloat16 g_hlo[(size_t)BB*NN*DD];
static __device__ __align__(256) __nv_bfloat16 g_ehi[(size_t)BB*RR*NN*NN];
static __device__ __align__(256) __nv_bfloat16 g_elo[(size_t)BB*RR*NN*NN];
static __device__ __align__(256) __nv_bfloat16 g_Whi[(size_t)RR*DD*DD];
static __device__ __align__(256) __nv_bfloat16 g_Wlo[(size_t)RR*DD*DD];
static __device__ __align__(256) __nv_bfloat16 g_wihhi[(size_t)TD*DD];
static __device__ __align__(256) __nv_bfloat16 g_wihlo[(size_t)TD*DD];
static __device__ __align__(256) __nv_bfloat16 g_whhhi[(size_t)TD*DD];
static __device__ __align__(256) __nv_bfloat16 g_whhlo[(size_t)TD*DD];
static __device__ __align__(256) __nv_bfloat16 g_hWhi[(size_t)RR*BB*NN*DD]; // [r][b*N+j][e]
static __device__ __align__(256) __nv_bfloat16 g_hWlo[(size_t)RR*BB*NN*DD];
static __device__ __align__(256) __nv_bfloat16 g_agghi[(size_t)BB*NN*DD];
static __device__ __align__(256) __nv_bfloat16 g_agglo[(size_t)BB*NN*DD];

// ---------------------------------------------------------------------------
// PTX helpers (all non-'a' ISA: cp.async / ldmatrix / mma.sync)
// ---------------------------------------------------------------------------
__device__ __forceinline__ uint32_t s2u(const void* p) {
  uint32_t a;
  asm("{ .reg .u64 t; cvta.to.shared.u64 t, %1; cvt.u32.u64 %0, t; }" : "=r"(a) : "l"(p));
  return a;
}
__device__ __forceinline__ void cp16(uint32_t s, const void* g) {
  asm volatile("cp.async.cg.shared.global [%0], [%1], 16;" :: "r"(s), "l"(g));
}
#define CP_COMMIT() asm volatile("cp.async.commit_group;" ::: "memory")

#define LDSM4(r, a) \
  asm volatile("ldmatrix.sync.aligned.m8n8.x4.shared.b16 {%0,%1,%2,%3},[%4];" \
    : "=r"((r)[0]),"=r"((r)[1]),"=r"((r)[2]),"=r"((r)[3]) : "r"(a))
#define LDSM4T(r, a) \
  asm volatile("ldmatrix.sync.aligned.m8n8.x4.trans.shared.b16 {%0,%1,%2,%3},[%4];" \
    : "=r"((r)[0]),"=r"((r)[1]),"=r"((r)[2]),"=r"((r)[3]) : "r"(a))

#define MMA(d, a, b0, b1) \
  asm volatile("mma.sync.aligned.m16n8k16.row.col.f32.bf16.bf16.f32 " \
    "{%0,%1,%2,%3},{%4,%5,%6,%7},{%8,%9},{%0,%1,%2,%3};" \
    : "+f"((d)[0]),"+f"((d)[1]),"+f"((d)[2]),"+f"((d)[3]) \
    : "r"((a)[0]),"r"((a)[1]),"r"((a)[2]),"r"((a)[3]),"r"(b0),"r"(b1))

// ---------------------------------------------------------------------------
// GEMM core: CTA 128x128x32, 8 warps (4M x 2N), warp tile 32x64
// Two B modes:
//   BT=false: B stored [n][k] (NT), non-trans ldmatrix, pitch 80B, 40960B/stage
//   BT=true : B stored [k][n] (row-major K x N), trans ldmatrix, pitch 272B,
//             37888B/stage. Fragment mapping: 4 sub-tiles at
//             (k0-7,n0-7),(k8-15,n0-7),(k0-7,n8-15),(k8-15,n8-15).
// ---------------------------------------------------------------------------
#define LDP 80    // A pitch (padded, bytes)
#define BTP 272   // B-trans pitch (128 e * 2B + 16 pad)

struct TilePtrs { const __nv_bfloat16 *ah, *al, *bh, *bl; };

template <bool BT, class F>
__device__ __forceinline__ void gemm_mma(F f, int niters, int lda, int ldb,
                                         float acc[2][8][4]) {
  constexpr uint32_t STB  = BT ? 37888u : 40960u;     // stage bytes
  constexpr uint32_t BLOD = BT ? 8704u  : 10240u;     // Blo offset from Bhi
  extern __shared__ char smem[];
  const uint32_t sb = s2u(smem);
  const int tid = threadIdx.x;
  const int lane = tid & 31, w = tid >> 5;
  const int wm = w & 3, wn = w >> 2;

  #pragma unroll
  for (int a = 0; a < 2; ++a)
    #pragma unroll
    for (int b = 0; b < 8; ++b)
      #pragma unroll
      for (int c = 0; c < 4; ++c) acc[a][b][c] = 0.f;

  auto load_stage = [&](int s, int it) {
    TilePtrs p = f(it);
    uint32_t st = sb + (uint32_t)s * STB;
    #pragma unroll
    for (int l = 0; l < 2; ++l) {
      int i = tid + l * 256;
      int r = i >> 2, c = i & 3;
      uint32_t o = (uint32_t)r * LDP + c * 16;
      cp16(st + o,         p.ah + (size_t)r * lda + c * 8);
      cp16(st + 10240 + o, p.al + (size_t)r * lda + c * 8);
      if (!BT) {
        cp16(st + 20480 + o, p.bh + (size_t)r * ldb + c * 8);
        cp16(st + 30720 + o, p.bl + (size_t)r * ldb + c * 8);
      } else {
        int rb = i >> 4, cb = i & 15;               // 32 k-rows x 16 chunks
        uint32_t ob = (uint32_t)rb * BTP + cb * 16;
        cp16(st + 20480 + ob,        p.bh + (size_t)rb * ldb + cb * 8);
        cp16(st + 20480 + BLOD + ob, p.bl + (size_t)rb * ldb + cb * 8);
      }
    }
    CP_COMMIT();
  };

  // ldmatrix lane address offsets
  const uint32_t aLane  = (uint32_t)(lane & 15) * LDP + (lane >> 4) * 16;
  const uint32_t bLane  = (uint32_t)((lane & 7) + ((lane >> 4) << 3)) * LDP
                        + ((lane >> 3) & 1) * 16;            // non-trans
  const uint32_t bLaneT = (uint32_t)((lane & 7) + ((lane >> 3) & 1) * 8) * BTP
                        + ((lane >> 4) & 1) * 16;            // trans

  load_stage(0, 0);
  for (int it = 0; it < niters; ++it) {
    if (it + 1 < niters) {
      load_stage((it + 1) & 1, it + 1);
      asm volatile("cp.async.wait_group 1;" ::: "memory");
    } else {
      asm volatile("cp.async.wait_group 0;" ::: "memory");
    }
    __syncthreads();
    uint32_t st = sb + (uint32_t)(it & 1) * STB;
    uint32_t aBase = st + (uint32_t)(wm * 32) * LDP + aLane;
    uint32_t bBase = BT ? (st + 20480 + (uint32_t)wn * 128 + bLaneT)
                        : (st + 20480 + (uint32_t)(wn * 64) * LDP + bLane);
    #pragma unroll
    for (int k16 = 0; k16 < 2; ++k16) {
      uint32_t ah[2][4], al[2][4], bh[4][4], bl[4][4];
      #pragma unroll
      for (int mt = 0; mt < 2; ++mt) {
        uint32_t a = aBase + (uint32_t)(mt * 16) * LDP + k16 * 32;
        LDSM4(ah[mt], a);
        LDSM4(al[mt], a + 10240);
      }
      #pragma unroll
      for (int g = 0; g < 4; ++g) {
        if (!BT) {
          uint32_t b = bBase + (uint32_t)(g * 16) * LDP + k16 * 32;
          LDSM4(bh[g], b);
          LDSM4(bl[g], b + BLOD);
        } else {
          uint32_t b = bBase + (uint32_t)k16 * (16 * BTP) + g * 32;
          LDSM4T(bh[g], b);
          LDSM4T(bl[g], b + BLOD);
        }
      }
      // Product-outermost: 16 independent accumulators between reuses.
      #pragma unroll
      for (int prod = 0; prod < 3; ++prod) {
        #pragma unroll
        for (int mt = 0; mt < 2; ++mt)
          #pragma unroll
          for (int g = 0; g < 4; ++g)
            #pragma unroll
            for (int t = 0; t < 2; ++t) {
              float* d = acc[mt][g * 2 + t];
              const uint32_t* A = (prod == 2) ? al[mt] : ah[mt];
              const uint32_t (&B)[4] = (prod == 1) ? bl[g] : bh[g];
              MMA(d, A, B[2*t], B[2*t+1]);
            }
      }
    }
    __syncthreads();
  }
}

// acc[mt][nt][cr] -> row = row0+wm*32+mt*16+(lane>>2)+((cr>>1)<<3)
//                    col = col0+wn*64+nt*8+(lane&3)*2+(cr&1)

// ---------------------------------------------------------------------------
// K1: hW[r][j][e] = sum_d h[j,d] * W[r][e,d]; natural [j][e] layout, coalesced
// grid (64, 4, 8)
// ---------------------------------------------------------------------------
__global__ void __launch_bounds__(256, 2) k_hw_t() {
  const int row0 = blockIdx.x * 128, col0 = blockIdx.y * 128, r = blockIdx.z;
  auto f = [&](int it) -> TilePtrs {
    int k0 = it * 32;
    TilePtrs p;
    p.ah = g_hhi + (size_t)row0 * DD + k0;
    p.al = g_hlo + (size_t)row0 * DD + k0;
    p.bh = g_Whi + ((size_t)r * DD + col0) * DD + k0;
    p.bl = g_Wlo + ((size_t)r * DD + col0) * DD + k0;
    return p;
  };
  float acc[2][8][4];
  gemm_mma<false>(f, 16, DD, DD, acc);
  const int lane = threadIdx.x & 31, w = threadIdx.x >> 5;
  const int wm = w & 3, wn = w >> 2, grp = lane >> 2, tig = lane & 3;
  #pragma unroll
  for (int mt = 0; mt < 2; ++mt)
    #pragma unroll
    for (int nt = 0; nt < 8; ++nt) {
      int j0 = row0 + wm * 32 + mt * 16 + grp;
      int e  = col0 + wn * 64 + nt * 8 + tig * 2;
      #pragma unroll
      for (int half = 0; half < 2; ++half) {       // cr pairs (0,1) / (2,3)
        float v0 = acc[mt][nt][half * 2 + 0];
        float v1 = acc[mt][nt][half * 2 + 1];
        size_t o = ((size_t)r * BB * NN + j0 + half * 8) * DD + e;
        __nv_bfloat162 hi = __floats2bfloat162_rn(v0, v1);
        *(__nv_bfloat162*)(g_hWhi + o) = hi;
        __nv_bfloat162 lo;
        lo.x = __float2bfloat16(v0 - __bfloat162float(hi.x));
        lo.y = __float2bfloat16(v1 - __bfloat162float(hi.y));
        *(__nv_bfloat162*)(g_hWlo + o) = lo;
      }
    }
}

// ---------------------------------------------------------------------------
// K2: agg[b][i][e] = sum_r sum_j edges[b,r,i,j]*hW[r][b*512+j][e] + bias_sum
// B loaded [k][n] with trans ldmatrix. grid (4, 4, 16); niters = 128
// ---------------------------------------------------------------------------
__global__ void __launch_bounds__(256, 2) k_agg_t() {
  const int b = blockIdx.z, row0 = blockIdx.x * 128, col0 = blockIdx.y * 128;
  auto f = [&](int it) -> TilePtrs {
    int r = it >> 4, k0 = (it & 15) * 32;
    TilePtrs p;
    size_t ea = ((size_t)(b * RR + r) * NN + row0) * NN + k0;
    size_t wb = ((size_t)r * BB * NN + (size_t)b * NN + k0) * DD + col0;
    p.ah = g_ehi + ea;  p.al = g_elo + ea;
    p.bh = g_hWhi + wb; p.bl = g_hWlo + wb;
    return p;
  };
  float acc[2][8][4];
  gemm_mma<true>(f, 128, NN, DD, acc);
  const int lane = threadIdx.x & 31, w = threadIdx.x >> 5;
  const int wm = w & 3, wn = w >> 2, grp = lane >> 2, tig = lane & 3;
  #pragma unroll
  for (int mt = 0; mt < 2; ++mt)
    #pragma unroll
    for (int nt = 0; nt < 8; ++nt)
      #pragma unroll
      for (int cr = 0; cr < 4; ++cr) {
        int i = row0 + wm * 32 + mt * 16 + grp + ((cr >> 1) << 3);
        int e = col0 + wn * 64 + nt * 8 + tig * 2 + (cr & 1);
        float v = acc[mt][nt][cr] + g_bias_sum[e];
        size_t o = (size_t)(b * NN + i) * DD + e;
        __nv_bfloat16 hh = __float2bfloat16(v);
        g_agghi[o] = hh;
        g_agglo[o] = __float2bfloat16(v - __bfloat162float(hh));
      }
}

// ---------------------------------------------------------------------------
// K3: gates, fused gi+gh: grid (64, 12, 2); z=0 -> gi (agg@w_ih), z=1 -> gh
// ---------------------------------------------------------------------------
__global__ void __launch_bounds__(256, 2) k_gates_t(const float* __restrict__ b_ih,
                                                    const float* __restrict__ b_hh) {
  const int z = blockIdx.z;
  const int row0 = blockIdx.x * 128, col0 = blockIdx.y * 128;
  const __nv_bfloat16* Ah = z ? g_hhi : g_agghi;
  const __nv_bfloat16* Al = z ? g_hlo : g_agglo;
  const __nv_bfloat16* Wh = z ? g_whhhi : g_wihhi;
  const __nv_bfloat16* Wl = z ? g_whhlo : g_wihlo;
  const float* bias = z ? b_hh : b_ih;
  float* C = z ? g_gh : g_gi;
  auto f = [&](int it) -> TilePtrs {
    int k0 = it * 32;
    TilePtrs p;
    p.ah = Ah + (size_t)row0 * DD + k0;
    p.al = Al + (size_t)row0 * DD + k0;
    p.bh = Wh + (size_t)col0 * DD + k0;
    p.bl = Wl + (size_t)col0 * DD + k0;
    return p;
  };
  float acc[2][8][4];
  gemm_mma<false>(f, 16, DD, DD, acc);
  const int lane = threadIdx.x & 31, w = threadIdx.x >> 5;
  const int wm = w & 3, wn = w >> 2, grp = lane >> 2, tig = lane & 3;
  #pragma unroll
  for (int mt = 0; mt < 2; ++mt)
    #pragma unroll
    for (int nt = 0; nt < 8; ++nt)
      #pragma unroll
      for (int cr = 0; cr < 4; ++cr) {
        int row = row0 + wm * 32 + mt * 16 + grp + ((cr >> 1) << 3);
        int e = col0 + wn * 64 + nt * 8 + tig * 2 + (cr & 1);
        C[(size_t)row * TD + e] = acc[mt][nt][cr] + bias[e];
      }
}

// ---------------------------------------------------------------------------
// Split & misc kernels
// ---------------------------------------------------------------------------
__global__ void k_split(const float4* __restrict__ s, __nv_bfloat162* __restrict__ hi,
                        __nv_bfloat162* __restrict__ lo, int n4) {
  int i = blockIdx.x * blockDim.x + threadIdx.x;
  if (i >= n4) return;
  float4 v = s[i];
  __nv_bfloat16 hx = __float2bfloat16(v.x), hy = __float2bfloat16(v.y);
  __nv_bfloat16 hz = __float2bfloat16(v.z), hw = __float2bfloat16(v.w);
  __nv_bfloat162 h0; h0.x = hx; h0.y = hy;
  __nv_bfloat162 h1; h1.x = hz; h1.y = hw;
  __nv_bfloat162 l0; l0.x = __float2bfloat16(v.x - __bfloat162float(hx));
                     l0.y = __float2bfloat16(v.y - __bfloat162float(hy));
  __nv_bfloat162 l1; l1.x = __float2bfloat16(v.z - __bfloat162float(hz));
                     l1.y = __float2bfloat16(v.w - __bfloat162float(hw));
  hi[2*i] = h0; hi[2*i+1] = h1;
  lo[2*i] = l0; lo[2*i+1] = l1;
}

__global__ void k_bias(const float* __restrict__ mb) {
  int d = threadIdx.x;
  float s = 0.f;
  #pragma unroll
  for (int r = 0; r < RR; ++r) s += mb[r * DD + d];
  g_bias_sum[d] = s;
}

__global__ void k_gru(const float* __restrict__ nodes, int step) {
  int idx = blockIdx.x * blockDim.x + threadIdx.x;
  const float* hsrc = (step == 0) ? nodes : g_h;
  int d = idx & (DD - 1);
  int row = idx >> 9;
  const float* gi = g_gi + (size_t)row * TD;
  const float* gh = g_gh + (size_t)row * TD;
  float ir = gi[d],        hr = gh[d];
  float iz = gi[DD + d],   hz = gh[DD + d];
  float in_ = gi[2*DD + d], hn = gh[2*DD + d];
  float r = 1.f / (1.f + __expf(-(ir + hr)));
  float z = 1.f / (1.f + __expf(-(iz + hz)));
  float targ = in_ + r * hn;
  float n = 1.f - 2.f / (1.f + __expf(2.f * targ));   // tanh
  float h = hsrc[idx];
  float hnew = (1.f - z) * n + z * h;
  g_h[idx] = hnew;
  __nv_bfloat16 hh = __float2bfloat16(hnew);
  g_hhi[idx] = hh;
  g_hlo[idx] = __float2bfloat16(hnew - __bfloat162float(hh));
}

// Two-phase mean: grid (BB, 8) x 512, then grid BB x 512
__global__ void k_mean1() {
  int b = blockIdx.x, seg = blockIdx.y, d = threadIdx.x;
  const float* hp = g_h + (size_t)b * NN * DD + (size_t)seg * 64 * DD + d;
  float s = 0.f;
  #pragma unroll 8
  for (int i = 0; i < 64; ++i) s += hp[(size_t)i * DD];
  g_msum[(size_t)(b * 8 + seg) * DD + d] = s;
}
__global__ void k_mean2(float* __restrict__ out) {
  int b = blockIdx.x, d = threadIdx.x;
  float s = 0.f;
  #pragma unroll
  for (int seg = 0; seg < 8; ++seg) s += g_msum[(size_t)(b * 8 + seg) * DD + d];
  out[b * DD + d] = s * (1.0f / NN);
}

// ---------------------------------------------------------------------------
extern "C" void kernel_launch(void* const* d_in, const int* in_sizes, int n_in,
                              void* d_out, int out_size) {
  const float* nodes = (const float*)d_in[0];
  const float* edges = (const float*)d_in[1];
  const float* msg_W = (const float*)d_in[2];
  const float* msg_b = (const float*)d_in[3];
  const float* b_ih  = (const float*)d_in[6];
  const float* b_hh  = (const float*)d_in[7];
  float* out = (float*)d_out;

  cudaFuncSetAttribute(k_hw_t,    cudaFuncAttributeMaxDynamicSharedMemorySize, 2*40960);
  cudaFuncSetAttribute(k_agg_t,   cudaFuncAttributeMaxDynamicSharedMemorySize, 2*37888);
  cudaFuncSetAttribute(k_gates_t, cudaFuncAttributeMaxDynamicSharedMemorySize, 2*40960);

  __nv_bfloat162 *hhi2, *hlo2, *ehi2, *elo2, *whi2, *wlo2, *ihhi2, *ihlo2, *hhhi2, *hhlo2;
  cudaGetSymbolAddress((void**)&hhi2,  g_hhi);   cudaGetSymbolAddress((void**)&hlo2,  g_hlo);
  cudaGetSymbolAddress((void**)&ehi2,  g_ehi);   cudaGetSymbolAddress((void**)&elo2,  g_elo);
  cudaGetSymbolAddress((void**)&whi2,  g_Whi);   cudaGetSymbolAddress((void**)&wlo2,  g_Wlo);
  cudaGetSymbolAddress((void**)&ihhi2, g_wihhi); cudaGetSymbolAddress((void**)&ihlo2, g_wihlo);
  cudaGetSymbolAddress((void**)&hhhi2, g_whhhi); cudaGetSymbolAddress((void**)&hhlo2, g_whhlo);

  int n4;
  n4 = BB*NN*DD/4;    k_split<<<n4/256, 256>>>((const float4*)nodes, hhi2, hlo2, n4);
  n4 = BB*RR*NN*NN/4; k_split<<<n4/256, 256>>>((const float4*)edges, ehi2, elo2, n4);
  n4 = RR*DD*DD/4;    k_split<<<n4/256, 256>>>((const float4*)msg_W, whi2, wlo2, n4);
  n4 = TD*DD/4;       k_split<<<n4/256, 256>>>((const float4*)d_in[4], ihhi2, ihlo2, n4);
  n4 = TD*DD/4;       k_split<<<n4/256, 256>>>((const float4*)d_in[5], hhhi2, hhlo2, n4);
  k_bias<<<1, DD>>>(msg_b);

  for (int s = 0; s < 2; ++s) {
    k_hw_t   <<<dim3(64, 4, 8),  256, 2*40960>>>();
    k_agg_t  <<<dim3(4, 4, 16),  256, 2*37888>>>();
    k_gates_t<<<dim3(64, 12, 2), 256, 2*40960>>>(b_ih, b_hh);
    k_gru    <<<(BB*NN*DD)/256, 256>>>(nodes, s);
  }
  k_mean1<<<dim3(BB, 8), DD>>>();
  k_mean2<<<BB, DD>>>(out);
}

// round 13
// speedup vs baseline: 1.3012x; 1.0807x over previous
#include <cuda_runtime.h>
#include <cuda_bf16.h>
#include <math.h>
#include <stdint.h>

// Problem dims
#define BB 16
#define NN 512
#define DD 512
#define RR 8
#define TD (3*DD)

// ---------------------------------------------------------------------------
// Scratch (__device__ globals; allocation-free)
// ---------------------------------------------------------------------------
static __device__ __align__(256) float g_h[(size_t)BB*NN*DD];
static __device__ __align__(256) float g_gi[(size_t)BB*NN*TD];
static __device__ __align__(256) float g_gh[(size_t)BB*NN*TD];
static __device__ __align__(256) float g_bias_sum[DD];
static __device__ __align__(256) float g_msum[(size_t)BB*8*DD];

static __device__ __align__(256) __nv_bfloat16 g_hhi[(size_t)BB*NN*DD];
static __device__ __align__(256) __nv_bfloat16 g_hlo[(size_t)BB*NN*DD];
static __device__ __align__(256) __nv_bfloat16 g_ehi[(size_t)BB*RR*NN*NN];
static __device__ __align__(256) __nv_bfloat16 g_elo[(size_t)BB*RR*NN*NN];
// Weights stored TRANSPOSED, K-major [k][n]:
static __device__ __align__(256) __nv_bfloat16 g_WThi[(size_t)RR*DD*DD];   // [r][d][e]
static __device__ __align__(256) __nv_bfloat16 g_WTlo[(size_t)RR*DD*DD];
static __device__ __align__(256) __nv_bfloat16 g_wihThi[(size_t)DD*TD];   // [d][3D]
static __device__ __align__(256) __nv_bfloat16 g_wihTlo[(size_t)DD*TD];
static __device__ __align__(256) __nv_bfloat16 g_whhThi[(size_t)DD*TD];
static __device__ __align__(256) __nv_bfloat16 g_whhTlo[(size_t)DD*TD];
static __device__ __align__(256) __nv_bfloat16 g_hWhi[(size_t)RR*BB*NN*DD]; // [r][b*N+j][e]
static __device__ __align__(256) __nv_bfloat16 g_hWlo[(size_t)RR*BB*NN*DD];
static __device__ __align__(256) __nv_bfloat16 g_agghi[(size_t)BB*NN*DD];
static __device__ __align__(256) __nv_bfloat16 g_agglo[(size_t)BB*NN*DD];

// ---------------------------------------------------------------------------
// PTX helpers (all non-'a' ISA: cp.async / ldmatrix / mma.sync)
// ---------------------------------------------------------------------------
__device__ __forceinline__ uint32_t s2u(const void* p) {
  uint32_t a;
  asm("{ .reg .u64 t; cvta.to.shared.u64 t, %1; cvt.u32.u64 %0, t; }" : "=r"(a) : "l"(p));
  return a;
}
__device__ __forceinline__ void cp16(uint32_t s, const void* g) {
  asm volatile("cp.async.cg.shared.global [%0], [%1], 16;" :: "r"(s), "l"(g));
}
#define CP_COMMIT() asm volatile("cp.async.commit_group;" ::: "memory")

#define LDSM4(r, a) \
  asm volatile("ldmatrix.sync.aligned.m8n8.x4.shared.b16 {%0,%1,%2,%3},[%4];" \
    : "=r"((r)[0]),"=r"((r)[1]),"=r"((r)[2]),"=r"((r)[3]) : "r"(a))
#define LDSM4T(r, a) \
  asm volatile("ldmatrix.sync.aligned.m8n8.x4.trans.shared.b16 {%0,%1,%2,%3},[%4];" \
    : "=r"((r)[0]),"=r"((r)[1]),"=r"((r)[2]),"=r"((r)[3]) : "r"(a))

#define MMA(d, a, b0, b1) \
  asm volatile("mma.sync.aligned.m16n8k16.row.col.f32.bf16.bf16.f32 " \
    "{%0,%1,%2,%3},{%4,%5,%6,%7},{%8,%9},{%0,%1,%2,%3};" \
    : "+f"((d)[0]),"+f"((d)[1]),"+f"((d)[2]),"+f"((d)[3]) \
    : "r"((a)[0]),"r"((a)[1]),"r"((a)[2]),"r"((a)[3]),"r"(b0),"r"(b1))

// ---------------------------------------------------------------------------
// GEMM core: CTA 128x128x32, 8 warps (4M x 2N), warp tile 32x64
// B ALWAYS K-major [k][n] + trans ldmatrix (BT mode).
// 3-stage cp.async pipeline, ONE __syncthreads per K-iteration.
// Stage: Ahi @0 | Alo @10240 | Bhi @20480 | Blo @29184; 37888 B/stage.
// 3 stages x 2 CTAs = 222 KB/SM -> 2 CTAs resident.
// ---------------------------------------------------------------------------
#define LDP 80      // A pitch (padded, bytes)
#define BTP 272     // B pitch (128 n * 2B + 16 pad)
#define STB 37888u  // stage bytes
#define BLOD 8704u  // Blo offset from Bhi
#define DYN_SMEM (3*37888)

struct TilePtrs { const __nv_bfloat16 *ah, *al, *bh, *bl; };

template <class F>
__device__ __forceinline__ void gemm_mma(F f, int niters, int lda, int ldb,
                                         float acc[2][8][4]) {
  extern __shared__ char smem[];
  const uint32_t sb = s2u(smem);
  const int tid = threadIdx.x;
  const int lane = tid & 31, w = tid >> 5;
  const int wm = w & 3, wn = w >> 2;

  #pragma unroll
  for (int a = 0; a < 2; ++a)
    #pragma unroll
    for (int b = 0; b < 8; ++b)
      #pragma unroll
      for (int c = 0; c < 4; ++c) acc[a][b][c] = 0.f;

  auto load_stage = [&](int s, int it) {
    TilePtrs p = f(it);
    uint32_t st = sb + (uint32_t)s * STB;
    #pragma unroll
    for (int l = 0; l < 2; ++l) {
      int i = tid + l * 256;
      int r = i >> 2, c = i & 3;                  // A: 128 rows x 4 chunks
      uint32_t o = (uint32_t)r * LDP + c * 16;
      cp16(st + o,         p.ah + (size_t)r * lda + c * 8);
      cp16(st + 10240 + o, p.al + (size_t)r * lda + c * 8);
      int rb = i >> 4, cb = i & 15;               // B: 32 k-rows x 16 chunks
      uint32_t ob = (uint32_t)rb * BTP + cb * 16;
      cp16(st + 20480 + ob,        p.bh + (size_t)rb * ldb + cb * 8);
      cp16(st + 20480 + BLOD + ob, p.bl + (size_t)rb * ldb + cb * 8);
    }
    CP_COMMIT();
  };

  // ldmatrix lane address offsets
  const uint32_t aLane  = (uint32_t)(lane & 15) * LDP + (lane >> 4) * 16;
  const uint32_t bLaneT = (uint32_t)((lane & 7) + ((lane >> 3) & 1) * 8) * BTP
                        + ((lane >> 4) & 1) * 16;

  load_stage(0, 0);
  if (niters > 1) load_stage(1, 1);

  int stage = 0;
  for (int it = 0; it < niters; ++it) {
    if (it + 1 < niters)
      asm volatile("cp.async.wait_group 1;" ::: "memory");
    else
      asm volatile("cp.async.wait_group 0;" ::: "memory");
    __syncthreads();           // buffer `stage` ready; prev compute done
    if (it + 2 < niters) {
      int ns = stage + 2; if (ns >= 3) ns -= 3;
      load_stage(ns, it + 2);  // writes the buffer consumed at iter it-1
    }
    uint32_t st = sb + (uint32_t)stage * STB;
    uint32_t aBase = st + (uint32_t)(wm * 32) * LDP + aLane;
    uint32_t bBase = st + 20480 + (uint32_t)wn * 128 + bLaneT;
    #pragma unroll
    for (int k16 = 0; k16 < 2; ++k16) {
      uint32_t ah[2][4], al[2][4], bh[4][4], bl[4][4];
      #pragma unroll
      for (int mt = 0; mt < 2; ++mt) {
        uint32_t a = aBase + (uint32_t)(mt * 16) * LDP + k16 * 32;
        LDSM4(ah[mt], a);
        LDSM4(al[mt], a + 10240);
      }
      #pragma unroll
      for (int g = 0; g < 4; ++g) {
        uint32_t b = bBase + (uint32_t)k16 * (16 * BTP) + g * 32;
        LDSM4T(bh[g], b);
        LDSM4T(bl[g], b + BLOD);
      }
      // Product-outermost: 16 independent accumulators between reuses.
      #pragma unroll
      for (int prod = 0; prod < 3; ++prod) {
        #pragma unroll
        for (int mt = 0; mt < 2; ++mt)
          #pragma unroll
          for (int g = 0; g < 4; ++g)
            #pragma unroll
            for (int t = 0; t < 2; ++t) {
              float* d = acc[mt][g * 2 + t];
              const uint32_t* A = (prod == 2) ? al[mt] : ah[mt];
              const uint32_t (&B)[4] = (prod == 1) ? bl[g] : bh[g];
              MMA(d, A, B[2*t], B[2*t+1]);
            }
      }
    }
    ++stage; if (stage >= 3) stage -= 3;
  }
}

// acc[mt][nt][cr] -> row = row0+wm*32+mt*16+(lane>>2)+((cr>>1)<<3)
//                    col = col0+wn*64+nt*8+(lane&3)*2+(cr&1)

// ---------------------------------------------------------------------------
// K1: hW[r][j][e] = sum_d h[j,d] * W[r][e,d];  B = WT[r][d][e] (K-major)
// grid (64, 4, 8)
// ---------------------------------------------------------------------------
__global__ void __launch_bounds__(256, 2) k_hw_t() {
  const int row0 = blockIdx.x * 128, col0 = blockIdx.y * 128, r = blockIdx.z;
  auto f = [&](int it) -> TilePtrs {
    int k0 = it * 32;
    TilePtrs p;
    p.ah = g_hhi + (size_t)row0 * DD + k0;
    p.al = g_hlo + (size_t)row0 * DD + k0;
    p.bh = g_WThi + ((size_t)r * DD + k0) * DD + col0;
    p.bl = g_WTlo + ((size_t)r * DD + k0) * DD + col0;
    return p;
  };
  float acc[2][8][4];
  gemm_mma(f, 16, DD, DD, acc);
  const int lane = threadIdx.x & 31, w = threadIdx.x >> 5;
  const int wm = w & 3, wn = w >> 2, grp = lane >> 2, tig = lane & 3;
  #pragma unroll
  for (int mt = 0; mt < 2; ++mt)
    #pragma unroll
    for (int nt = 0; nt < 8; ++nt) {
      int j0 = row0 + wm * 32 + mt * 16 + grp;
      int e  = col0 + wn * 64 + nt * 8 + tig * 2;
      #pragma unroll
      for (int half = 0; half < 2; ++half) {
        float v0 = acc[mt][nt][half * 2 + 0];
        float v1 = acc[mt][nt][half * 2 + 1];
        size_t o = ((size_t)r * BB * NN + j0 + half * 8) * DD + e;
        __nv_bfloat162 hi = __floats2bfloat162_rn(v0, v1);
        *(__nv_bfloat162*)(g_hWhi + o) = hi;
        __nv_bfloat162 lo;
        lo.x = __float2bfloat16(v0 - __bfloat162float(hi.x));
        lo.y = __float2bfloat16(v1 - __bfloat162float(hi.y));
        *(__nv_bfloat162*)(g_hWlo + o) = lo;
      }
    }
}

// ---------------------------------------------------------------------------
// K2: agg[b][i][e] = sum_r sum_j edges[b,r,i,j]*hW[r][b*512+j][e] + bias_sum
// grid (4, 4, 16); niters = 128
// ---------------------------------------------------------------------------
__global__ void __launch_bounds__(256, 2) k_agg_t() {
  const int b = blockIdx.z, row0 = blockIdx.x * 128, col0 = blockIdx.y * 128;
  auto f = [&](int it) -> TilePtrs {
    int r = it >> 4, k0 = (it & 15) * 32;
    TilePtrs p;
    size_t ea = ((size_t)(b * RR + r) * NN + row0) * NN + k0;
    size_t wb = ((size_t)r * BB * NN + (size_t)b * NN + k0) * DD + col0;
    p.ah = g_ehi + ea;  p.al = g_elo + ea;
    p.bh = g_hWhi + wb; p.bl = g_hWlo + wb;
    return p;
  };
  float acc[2][8][4];
  gemm_mma(f, 128, NN, DD, acc);
  const int lane = threadIdx.x & 31, w = threadIdx.x >> 5;
  const int wm = w & 3, wn = w >> 2, grp = lane >> 2, tig = lane & 3;
  #pragma unroll
  for (int mt = 0; mt < 2; ++mt)
    #pragma unroll
    for (int nt = 0; nt < 8; ++nt)
      #pragma unroll
      for (int cr = 0; cr < 4; ++cr) {
        int i = row0 + wm * 32 + mt * 16 + grp + ((cr >> 1) << 3);
        int e = col0 + wn * 64 + nt * 8 + tig * 2 + (cr & 1);
        float v = acc[mt][nt][cr] + g_bias_sum[e];
        size_t o = (size_t)(b * NN + i) * DD + e;
        __nv_bfloat16 hh = __float2bfloat16(v);
        g_agghi[o] = hh;
        g_agglo[o] = __float2bfloat16(v - __bfloat162float(hh));
      }
}

// ---------------------------------------------------------------------------
// K3: gates, fused: grid (64, 12, 2); z=0 -> gi (agg@w_ih), z=1 -> gh (h@w_hh)
// B = wT [512][1536] (K-major)
// ---------------------------------------------------------------------------
__global__ void __launch_bounds__(256, 2) k_gates_t(const float* __restrict__ b_ih,
                                                    const float* __restrict__ b_hh) {
  const int z = blockIdx.z;
  const int row0 = blockIdx.x * 128, col0 = blockIdx.y * 128;
  const __nv_bfloat16* Ah = z ? g_hhi : g_agghi;
  const __nv_bfloat16* Al = z ? g_hlo : g_agglo;
  const __nv_bfloat16* Wh = z ? g_whhThi : g_wihThi;
  const __nv_bfloat16* Wl = z ? g_whhTlo : g_wihTlo;
  const float* bias = z ? b_hh : b_ih;
  float* C = z ? g_gh : g_gi;
  auto f = [&](int it) -> TilePtrs {
    int k0 = it * 32;
    TilePtrs p;
    p.ah = Ah + (size_t)row0 * DD + k0;
    p.al = Al + (size_t)row0 * DD + k0;
    p.bh = Wh + (size_t)k0 * TD + col0;
    p.bl = Wl + (size_t)k0 * TD + col0;
    return p;
  };
  float acc[2][8][4];
  gemm_mma(f, 16, DD, TD, acc);
  const int lane = threadIdx.x & 31, w = threadIdx.x >> 5;
  const int wm = w & 3, wn = w >> 2, grp = lane >> 2, tig = lane & 3;
  #pragma unroll
  for (int mt = 0; mt < 2; ++mt)
    #pragma unroll
    for (int nt = 0; nt < 8; ++nt)
      #pragma unroll
      for (int cr = 0; cr < 4; ++cr) {
        int row = row0 + wm * 32 + mt * 16 + grp + ((cr >> 1) << 3);
        int e = col0 + wn * 64 + nt * 8 + tig * 2 + (cr & 1);
        C[(size_t)row * TD + e] = acc[mt][nt][cr] + bias[e];
      }
}

// ---------------------------------------------------------------------------
// Split & misc kernels
// ---------------------------------------------------------------------------
__global__ void k_split(const float4* __restrict__ s, __nv_bfloat162* __restrict__ hi,
                        __nv_bfloat162* __restrict__ lo, int n4) {
  int i = blockIdx.x * blockDim.x + threadIdx.x;
  if (i >= n4) return;
  float4 v = s[i];
  __nv_bfloat16 hx = __float2bfloat16(v.x), hy = __float2bfloat16(v.y);
  __nv_bfloat16 hz = __float2bfloat16(v.z), hw = __float2bfloat16(v.w);
  __nv_bfloat162 h0; h0.x = hx; h0.y = hy;
  __nv_bfloat162 h1; h1.x = hz; h1.y = hw;
  __nv_bfloat162 l0; l0.x = __float2bfloat16(v.x - __bfloat162float(hx));
                     l0.y = __float2bfloat16(v.y - __bfloat162float(hy));
  __nv_bfloat162 l1; l1.x = __float2bfloat16(v.z - __bfloat162float(hz));
                     l1.y = __float2bfloat16(v.w - __bfloat162float(hw));
  hi[2*i] = h0; hi[2*i+1] = h1;
  lo[2*i] = l0; lo[2*i+1] = l1;
}

// Transpose + split: src [nrows][ncols] fp32 -> dst [ncols][nrows] bf16 hi/lo
__global__ void k_tsplit(const float* __restrict__ src, __nv_bfloat16* __restrict__ hi,
                         __nv_bfloat16* __restrict__ lo, int nrows, int ncols) {
  __shared__ float t[32][33];
  int z = blockIdx.z;
  src += (size_t)z * nrows * ncols;
  hi  += (size_t)z * nrows * ncols;
  lo  += (size_t)z * nrows * ncols;
  int c0 = blockIdx.x * 32, r0 = blockIdx.y * 32;
  int tx = threadIdx.x, ty = threadIdx.y;
  #pragma unroll
  for (int i = ty; i < 32; i += 8)
    t[i][tx] = src[(size_t)(r0 + i) * ncols + c0 + tx];
  __syncthreads();
  #pragma unroll
  for (int j = ty; j < 32; j += 8) {
    float v = t[tx][j];
    size_t o = (size_t)(c0 + j) * nrows + r0 + tx;
    __nv_bfloat16 h = __float2bfloat16(v);
    hi[o] = h;
    lo[o] = __float2bfloat16(v - __bfloat162float(h));
  }
}

__global__ void k_bias(const float* __restrict__ mb) {
  int d = threadIdx.x;
  float s = 0.f;
  #pragma unroll
  for (int r = 0; r < RR; ++r) s += mb[r * DD + d];
  g_bias_sum[d] = s;
}

__global__ void k_gru(const float* __restrict__ nodes, int step) {
  int idx = blockIdx.x * blockDim.x + threadIdx.x;
  const float* hsrc = (step == 0) ? nodes : g_h;
  int d = idx & (DD - 1);
  int row = idx >> 9;
  const float* gi = g_gi + (size_t)row * TD;
  const float* gh = g_gh + (size_t)row * TD;
  float ir = gi[d],        hr = gh[d];
  float iz = gi[DD + d],   hz = gh[DD + d];
  float in_ = gi[2*DD + d], hn = gh[2*DD + d];
  float r = 1.f / (1.f + __expf(-(ir + hr)));
  float z = 1.f / (1.f + __expf(-(iz + hz)));
  float targ = in_ + r * hn;
  float n = 1.f - 2.f / (1.f + __expf(2.f * targ));   // tanh
  float h = hsrc[idx];
  float hnew = (1.f - z) * n + z * h;
  g_h[idx] = hnew;
  __nv_bfloat16 hh = __float2bfloat16(hnew);
  g_hhi[idx] = hh;
  g_hlo[idx] = __float2bfloat16(hnew - __bfloat162float(hh));
}

// Two-phase mean
__global__ void k_mean1() {
  int b = blockIdx.x, seg = blockIdx.y, d = threadIdx.x;
  const float* hp = g_h + (size_t)b * NN * DD + (size_t)seg * 64 * DD + d;
  float s = 0.f;
  #pragma unroll 8
  for (int i = 0; i < 64; ++i) s += hp[(size_t)i * DD];
  g_msum[(size_t)(b * 8 + seg) * DD + d] = s;
}
__global__ void k_mean2(float* __restrict__ out) {
  int b = blockIdx.x, d = threadIdx.x;
  float s = 0.f;
  #pragma unroll
  for (int seg = 0; seg < 8; ++seg) s += g_msum[(size_t)(b * 8 + seg) * DD + d];
  out[b * DD + d] = s * (1.0f / NN);
}

// ---------------------------------------------------------------------------
extern "C" void kernel_launch(void* const* d_in, const int* in_sizes, int n_in,
                              void* d_out, int out_size) {
  const float* nodes = (const float*)d_in[0];
  const float* edges = (const float*)d_in[1];
  const float* msg_W = (const float*)d_in[2];
  const float* msg_b = (const float*)d_in[3];
  const float* w_ih  = (const float*)d_in[4];
  const float* w_hh  = (const float*)d_in[5];
  const float* b_ih  = (const float*)d_in[6];
  const float* b_hh  = (const float*)d_in[7];
  float* out = (float*)d_out;

  cudaFuncSetAttribute(k_hw_t,    cudaFuncAttributeMaxDynamicSharedMemorySize, DYN_SMEM);
  cudaFuncSetAttribute(k_agg_t,   cudaFuncAttributeMaxDynamicSharedMemorySize, DYN_SMEM);
  cudaFuncSetAttribute(k_gates_t, cudaFuncAttributeMaxDynamicSharedMemorySize, DYN_SMEM);

  __nv_bfloat162 *hhi2, *hlo2, *ehi2, *elo2;
  __nv_bfloat16 *wthi, *wtlo, *ihthi, *ihtlo, *hhthi, *hhtlo;
  cudaGetSymbolAddress((void**)&hhi2,  g_hhi);    cudaGetSymbolAddress((void**)&hlo2,  g_hlo);
  cudaGetSymbolAddress((void**)&ehi2,  g_ehi);    cudaGetSymbolAddress((void**)&elo2,  g_elo);
  cudaGetSymbolAddress((void**)&wthi,  g_WThi);   cudaGetSymbolAddress((void**)&wtlo,  g_WTlo);
  cudaGetSymbolAddress((void**)&ihthi, g_wihThi); cudaGetSymbolAddress((void**)&ihtlo, g_wihTlo);
  cudaGetSymbolAddress((void**)&hhthi, g_whhThi); cudaGetSymbolAddress((void**)&hhtlo, g_whhTlo);

  int n4;
  n4 = BB*NN*DD/4;    k_split<<<n4/256, 256>>>((const float4*)nodes, hhi2, hlo2, n4);
  n4 = BB*RR*NN*NN/4; k_split<<<n4/256, 256>>>((const float4*)edges, ehi2, elo2, n4);
  // Transposed weight splits (K-major B operands)
  k_tsplit<<<dim3(16, 16, 8), dim3(32, 8)>>>(msg_W, wthi, wtlo, DD, DD);
  k_tsplit<<<dim3(16, 48, 1), dim3(32, 8)>>>(w_ih, ihthi, ihtlo, TD, DD);
  k_tsplit<<<dim3(16, 48, 1), dim3(32, 8)>>>(w_hh, hhthi, hhtlo, TD, DD);
  k_bias<<<1, DD>>>(msg_b);

  for (int s = 0; s < 2; ++s) {
    k_hw_t   <<<dim3(64, 4, 8),  256, DYN_SMEM>>>();
    k_agg_t  <<<dim3(4, 4, 16),  256, DYN_SMEM>>>();
    k_gates_t<<<dim3(64, 12, 2), 256, DYN_SMEM>>>(b_ih, b_hh);
    k_gru    <<<(BB*NN*DD)/256, 256>>>(nodes, s);
  }
  k_mean1<<<dim3(BB, 8), DD>>>();
  k_mean2<<<BB, DD>>>(out);
}

// round 16
// speedup vs baseline: 1.3928x; 1.0704x over previous
#include <cuda_runtime.h>
#include <cuda_bf16.h>
#include <math.h>
#include <stdint.h>

// Problem dims
#define BB 16
#define NN 512
#define DD 512
#define RR 8
#define TD (3*DD)

// ---------------------------------------------------------------------------
// Scratch (__device__ globals; allocation-free)
// ---------------------------------------------------------------------------
static __device__ __align__(256) float g_h[(size_t)BB*NN*DD];
static __device__ __align__(256) float g_gi[(size_t)BB*NN*TD];
static __device__ __align__(256) float g_gh[(size_t)BB*NN*TD];
static __device__ __align__(256) float g_bias_sum[DD];
static __device__ __align__(256) float g_msum[(size_t)BB*8*DD];
static __device__ __align__(256) float g_hsum[(size_t)BB*DD];     // sum_j h[b,j,d]
static __device__ __align__(256) float g_WsumT[(size_t)DD*DD];    // [e][d] = sum_r W[r][e][d]
static __device__ __align__(256) float g_T[(size_t)BB*DD];        // DC correction

static __device__ __align__(256) __nv_bfloat16 g_hhi[(size_t)BB*NN*DD];
static __device__ __align__(256) __nv_bfloat16 g_hlo[(size_t)BB*NN*DD];
static __device__ __align__(256) __nv_bfloat16 g_ehi[(size_t)BB*RR*NN*NN];  // bf16(e - 0.5)
// Weights stored TRANSPOSED, K-major [k][n]:
static __device__ __align__(256) __nv_bfloat16 g_WThi[(size_t)RR*DD*DD];   // [r][d][e]
static __device__ __align__(256) __nv_bfloat16 g_WTlo[(size_t)RR*DD*DD];
static __device__ __align__(256) __nv_bfloat16 g_wihThi[(size_t)DD*TD];   // [d][3D]
static __device__ __align__(256) __nv_bfloat16 g_wihTlo[(size_t)DD*TD];
static __device__ __align__(256) __nv_bfloat16 g_whhThi[(size_t)DD*TD];
static __device__ __align__(256) __nv_bfloat16 g_whhTlo[(size_t)DD*TD];
static __device__ __align__(256) __nv_bfloat16 g_hWhi[(size_t)RR*BB*NN*DD]; // [r][b*N+j][e]
static __device__ __align__(256) __nv_bfloat16 g_hWlo[(size_t)RR*BB*NN*DD];
static __device__ __align__(256) __nv_bfloat16 g_agghi[(size_t)BB*NN*DD];
static __device__ __align__(256) __nv_bfloat16 g_agglo[(size_t)BB*NN*DD];

// ---------------------------------------------------------------------------
// PTX helpers (all non-'a' ISA: cp.async / ldmatrix / mma.sync)
// ---------------------------------------------------------------------------
__device__ __forceinline__ uint32_t s2u(const void* p) {
  uint32_t a;
  asm("{ .reg .u64 t; cvta.to.shared.u64 t, %1; cvt.u32.u64 %0, t; }" : "=r"(a) : "l"(p));
  return a;
}
__device__ __forceinline__ void cp16(uint32_t s, const void* g) {
  asm volatile("cp.async.cg.shared.global [%0], [%1], 16;" :: "r"(s), "l"(g));
}
#define CP_COMMIT() asm volatile("cp.async.commit_group;" ::: "memory")

#define LDSM4(r, a) \
  asm volatile("ldmatrix.sync.aligned.m8n8.x4.shared.b16 {%0,%1,%2,%3},[%4];" \
    : "=r"((r)[0]),"=r"((r)[1]),"=r"((r)[2]),"=r"((r)[3]) : "r"(a))
#define LDSM4T(r, a) \
  asm volatile("ldmatrix.sync.aligned.m8n8.x4.trans.shared.b16 {%0,%1,%2,%3},[%4];" \
    : "=r"((r)[0]),"=r"((r)[1]),"=r"((r)[2]),"=r"((r)[3]) : "r"(a))

#define MMA(d, a, b0, b1) \
  asm volatile("mma.sync.aligned.m16n8k16.row.col.f32.bf16.bf16.f32 " \
    "{%0,%1,%2,%3},{%4,%5,%6,%7},{%8,%9},{%0,%1,%2,%3};" \
    : "+f"((d)[0]),"+f"((d)[1]),"+f"((d)[2]),"+f"((d)[3]) \
    : "r"((a)[0]),"r"((a)[1]),"r"((a)[2]),"r"((a)[3]),"r"(b0),"r"(b1))

// ---------------------------------------------------------------------------
// GEMM core: CTA 128x128x32, 8 warps (4M x 2N), warp tile 32x64
// B ALWAYS K-major [k][n] + trans ldmatrix.
// ALO=true : A hi+lo (3 products), 3-stage, 37888 B/stage
// ALO=false: A hi only (2 products), 4-stage, 27648 B/stage
// Both: 2 CTAs/SM; ONE __syncthreads per K-iteration.
// ---------------------------------------------------------------------------
#define LDP 80      // A pitch (padded, bytes)
#define BTP 272     // B pitch (128 n * 2B + 16 pad)

struct TilePtrs { const __nv_bfloat16 *ah, *al, *bh, *bl; };

template <bool ALO, class F>
__device__ __forceinline__ void gemm_mma(F f, int niters, int lda, int ldb,
                                         float acc[2][8][4]) {
  constexpr uint32_t BOFF = ALO ? 20480u : 10240u;     // Bhi offset
  constexpr uint32_t BLOD = 8704u;                     // Blo offset from Bhi
  constexpr uint32_t STB  = ALO ? 37888u : 27648u;     // stage bytes
  constexpr int NSTG = ALO ? 3 : 4;
  extern __shared__ char smem[];
  const uint32_t sb = s2u(smem);
  const int tid = threadIdx.x;
  const int lane = tid & 31, w = tid >> 5;
  const int wm = w & 3, wn = w >> 2;

  #pragma unroll
  for (int a = 0; a < 2; ++a)
    #pragma unroll
    for (int b = 0; b < 8; ++b)
      #pragma unroll
      for (int c = 0; c < 4; ++c) acc[a][b][c] = 0.f;

  auto load_stage = [&](int s, int it) {
    TilePtrs p = f(it);
    uint32_t st = sb + (uint32_t)s * STB;
    #pragma unroll
    for (int l = 0; l < 2; ++l) {
      int i = tid + l * 256;
      int r = i >> 2, c = i & 3;                  // A: 128 rows x 4 chunks
      uint32_t o = (uint32_t)r * LDP + c * 16;
      cp16(st + o, p.ah + (size_t)r * lda + c * 8);
      if (ALO) cp16(st + 10240 + o, p.al + (size_t)r * lda + c * 8);
      int rb = i >> 4, cb = i & 15;               // B: 32 k-rows x 16 chunks
      uint32_t ob = (uint32_t)rb * BTP + cb * 16;
      cp16(st + BOFF + ob,        p.bh + (size_t)rb * ldb + cb * 8);
      cp16(st + BOFF + BLOD + ob, p.bl + (size_t)rb * ldb + cb * 8);
    }
    CP_COMMIT();
  };

  const uint32_t aLane  = (uint32_t)(lane & 15) * LDP + (lane >> 4) * 16;
  const uint32_t bLaneT = (uint32_t)((lane & 7) + ((lane >> 3) & 1) * 8) * BTP
                        + ((lane >> 4) & 1) * 16;

  load_stage(0, 0);
  if (niters > 1) load_stage(1, 1);
  if (!ALO && niters > 2) load_stage(2, 2);

  int stage = 0;
  for (int it = 0; it < niters; ++it) {
    int rem = niters - 1 - it;   // groups issued after group `it`
    if (ALO) {
      if (rem >= 1) asm volatile("cp.async.wait_group 1;" ::: "memory");
      else          asm volatile("cp.async.wait_group 0;" ::: "memory");
    } else {
      if (rem >= 2)      asm volatile("cp.async.wait_group 2;" ::: "memory");
      else if (rem == 1) asm volatile("cp.async.wait_group 1;" ::: "memory");
      else               asm volatile("cp.async.wait_group 0;" ::: "memory");
    }
    __syncthreads();             // stage ready; all warps done with it-1
    if (it + NSTG - 1 < niters) {
      int ns = stage + NSTG - 1; if (ns >= NSTG) ns -= NSTG;
      load_stage(ns, it + NSTG - 1);   // overwrites buffer of iter it-1
    }
    uint32_t st = sb + (uint32_t)stage * STB;
    uint32_t aBase = st + (uint32_t)(wm * 32) * LDP + aLane;
    uint32_t bBase = st + BOFF + (uint32_t)wn * 128 + bLaneT;
    #pragma unroll
    for (int k16 = 0; k16 < 2; ++k16) {
      uint32_t ah[2][4], al[2][4], bh[4][4], bl[4][4];
      #pragma unroll
      for (int mt = 0; mt < 2; ++mt) {
        uint32_t a = aBase + (uint32_t)(mt * 16) * LDP + k16 * 32;
        LDSM4(ah[mt], a);
        if (ALO) LDSM4(al[mt], a + 10240);
      }
      #pragma unroll
      for (int g = 0; g < 4; ++g) {
        uint32_t b = bBase + (uint32_t)k16 * (16 * BTP) + g * 32;
        LDSM4T(bh[g], b);
        LDSM4T(bl[g], b + BLOD);
      }
      // Product-outermost: 16 independent accumulators between reuses.
      #pragma unroll
      for (int prod = 0; prod < (ALO ? 3 : 2); ++prod) {
        #pragma unroll
        for (int mt = 0; mt < 2; ++mt)
          #pragma unroll
          for (int g = 0; g < 4; ++g)
            #pragma unroll
            for (int t = 0; t < 2; ++t) {
              float* d = acc[mt][g * 2 + t];
              const uint32_t* A = (ALO && prod == 2) ? al[mt] : ah[mt];
              const uint32_t (&B)[4] = (prod == 1) ? bl[g] : bh[g];
              MMA(d, A, B[2*t], B[2*t+1]);
            }
      }
    }
    ++stage; if (stage >= NSTG) stage -= NSTG;
  }
}

// acc[mt][nt][cr] -> row = row0+wm*32+mt*16+(lane>>2)+((cr>>1)<<3)
//                    col = col0+wn*64+nt*8+(lane&3)*2+(cr&1)

// ---------------------------------------------------------------------------
// K1: hW[r][j][e] = sum_d h[j,d] * W[r][e,d];  B = WT[r][d][e] (K-major)
// grid (64, 4, 8)
// ---------------------------------------------------------------------------
__global__ void __launch_bounds__(256, 2) k_hw_t() {
  const int row0 = blockIdx.x * 128, col0 = blockIdx.y * 128, r = blockIdx.z;
  auto f = [&](int it) -> TilePtrs {
    int k0 = it * 32;
    TilePtrs p;
    p.ah = g_hhi + (size_t)row0 * DD + k0;
    p.al = g_hlo + (size_t)row0 * DD + k0;
    p.bh = g_WThi + ((size_t)r * DD + k0) * DD + col0;
    p.bl = g_WTlo + ((size_t)r * DD + k0) * DD + col0;
    return p;
  };
  float acc[2][8][4];
  gemm_mma<true>(f, 16, DD, DD, acc);
  const int lane = threadIdx.x & 31, w = threadIdx.x >> 5;
  const int wm = w & 3, wn = w >> 2, grp = lane >> 2, tig = lane & 3;
  #pragma unroll
  for (int mt = 0; mt < 2; ++mt)
    #pragma unroll
    for (int nt = 0; nt < 8; ++nt) {
      int j0 = row0 + wm * 32 + mt * 16 + grp;
      int e  = col0 + wn * 64 + nt * 8 + tig * 2;
      #pragma unroll
      for (int half = 0; half < 2; ++half) {
        float v0 = acc[mt][nt][half * 2 + 0];
        float v1 = acc[mt][nt][half * 2 + 1];
        size_t o = ((size_t)r * BB * NN + j0 + half * 8) * DD + e;
        __nv_bfloat162 hi = __floats2bfloat162_rn(v0, v1);
        *(__nv_bfloat162*)(g_hWhi + o) = hi;
        __nv_bfloat162 lo;
        lo.x = __float2bfloat16(v0 - __bfloat162float(hi.x));
        lo.y = __float2bfloat16(v1 - __bfloat162float(hi.y));
        *(__nv_bfloat162*)(g_hWlo + o) = lo;
      }
    }
}

// ---------------------------------------------------------------------------
// K2: agg[b][i][e] = sum_r sum_j (0.5+delta)[...]*hW + bias_sum
//   GEMM on delta_hi (2 products, 4-stage); DC term added from g_T (fp32 exact)
// grid (4, 4, 16); niters = 128
// ---------------------------------------------------------------------------
__global__ void __launch_bounds__(256, 2) k_agg_t() {
  const int b = blockIdx.z, row0 = blockIdx.x * 128, col0 = blockIdx.y * 128;
  auto f = [&](int it) -> TilePtrs {
    int r = it >> 4, k0 = (it & 15) * 32;
    TilePtrs p;
    size_t ea = ((size_t)(b * RR + r) * NN + row0) * NN + k0;
    size_t wb = ((size_t)r * BB * NN + (size_t)b * NN + k0) * DD + col0;
    p.ah = g_ehi + ea;  p.al = nullptr;
    p.bh = g_hWhi + wb; p.bl = g_hWlo + wb;
    return p;
  };
  float acc[2][8][4];
  gemm_mma<false>(f, 128, NN, DD, acc);
  const int lane = threadIdx.x & 31, w = threadIdx.x >> 5;
  const int wm = w & 3, wn = w >> 2, grp = lane >> 2, tig = lane & 3;
  #pragma unroll
  for (int mt = 0; mt < 2; ++mt)
    #pragma unroll
    for (int nt = 0; nt < 8; ++nt)
      #pragma unroll
      for (int cr = 0; cr < 4; ++cr) {
        int i = row0 + wm * 32 + mt * 16 + grp + ((cr >> 1) << 3);
        int e = col0 + wn * 64 + nt * 8 + tig * 2 + (cr & 1);
        float v = acc[mt][nt][cr] + g_T[(size_t)b * DD + e] + g_bias_sum[e];
        size_t o = (size_t)(b * NN + i) * DD + e;
        __nv_bfloat16 hh = __float2bfloat16(v);
        g_agghi[o] = hh;
        g_agglo[o] = __float2bfloat16(v - __bfloat162float(hh));
      }
}

// ---------------------------------------------------------------------------
// K3: gates, fused: grid (64, 12, 2); z=0 -> gi (agg@w_ih), z=1 -> gh (h@w_hh)
// ---------------------------------------------------------------------------
__global__ void __launch_bounds__(256, 2) k_gates_t(const float* __restrict__ b_ih,
                                                    const float* __restrict__ b_hh) {
  const int z = blockIdx.z;
  const int row0 = blockIdx.x * 128, col0 = blockIdx.y * 128;
  const __nv_bfloat16* Ah = z ? g_hhi : g_agghi;
  const __nv_bfloat16* Al = z ? g_hlo : g_agglo;
  const __nv_bfloat16* Wh = z ? g_whhThi : g_wihThi;
  const __nv_bfloat16* Wl = z ? g_whhTlo : g_wihTlo;
  const float* bias = z ? b_hh : b_ih;
  float* C = z ? g_gh : g_gi;
  auto f = [&](int it) -> TilePtrs {
    int k0 = it * 32;
    TilePtrs p;
    p.ah = Ah + (size_t)row0 * DD + k0;
    p.al = Al + (size_t)row0 * DD + k0;
    p.bh = Wh + (size_t)k0 * TD + col0;
    p.bl = Wl + (size_t)k0 * TD + col0;
    return p;
  };
  float acc[2][8][4];
  gemm_mma<true>(f, 16, DD, TD, acc);
  const int lane = threadIdx.x & 31, w = threadIdx.x >> 5;
  const int wm = w & 3, wn = w >> 2, grp = lane >> 2, tig = lane & 3;
  #pragma unroll
  for (int mt = 0; mt < 2; ++mt)
    #pragma unroll
    for (int nt = 0; nt < 8; ++nt)
      #pragma unroll
      for (int cr = 0; cr < 4; ++cr) {
        int row = row0 + wm * 32 + mt * 16 + grp + ((cr >> 1) << 3);
        int e = col0 + wn * 64 + nt * 8 + tig * 2 + (cr & 1);
        C[(size_t)row * TD + e] = acc[mt][nt][cr] + bias[e];
      }
}

// ---------------------------------------------------------------------------
// Split & misc kernels
// ---------------------------------------------------------------------------
__global__ void k_split(const float4* __restrict__ s, __nv_bfloat162* __restrict__ hi,
                        __nv_bfloat162* __restrict__ lo, int n4) {
  int i = blockIdx.x * blockDim.x + threadIdx.x;
  if (i >= n4) return;
  float4 v = s[i];
  __nv_bfloat16 hx = __float2bfloat16(v.x), hy = __float2bfloat16(v.y);
  __nv_bfloat16 hz = __float2bfloat16(v.z), hw = __float2bfloat16(v.w);
  __nv_bfloat162 h0; h0.x = hx; h0.y = hy;
  __nv_bfloat162 h1; h1.x = hz; h1.y = hw;
  __nv_bfloat162 l0; l0.x = __float2bfloat16(v.x - __bfloat162float(hx));
                     l0.y = __float2bfloat16(v.y - __bfloat162float(hy));
  __nv_bfloat162 l1; l1.x = __float2bfloat16(v.z - __bfloat162float(hz));
                     l1.y = __float2bfloat16(v.w - __bfloat162float(hw));
  hi[2*i] = h0; hi[2*i+1] = h1;
  lo[2*i] = l0; lo[2*i+1] = l1;
}

// edges -> bf16(e - 0.5): centered operand halves quantization residual
__global__ void k_split_delta(const float4* __restrict__ s,
                              __nv_bfloat162* __restrict__ hi, int n4) {
  int i = blockIdx.x * blockDim.x + threadIdx.x;
  if (i >= n4) return;
  float4 v = s[i];
  __nv_bfloat162 h0; h0.x = __float2bfloat16(v.x - 0.5f);
                     h0.y = __float2bfloat16(v.y - 0.5f);
  __nv_bfloat162 h1; h1.x = __float2bfloat16(v.z - 0.5f);
                     h1.y = __float2bfloat16(v.w - 0.5f);
  hi[2*i] = h0; hi[2*i+1] = h1;
}

// Transpose + split: src [nrows][ncols] fp32 -> dst [ncols][nrows] bf16 hi/lo
__global__ void k_tsplit(const float* __restrict__ src, __nv_bfloat16* __restrict__ hi,
                         __nv_bfloat16* __restrict__ lo, int nrows, int ncols) {
  __shared__ float t[32][33];
  int z = blockIdx.z;
  src += (size_t)z * nrows * ncols;
  hi  += (size_t)z * nrows * ncols;
  lo  += (size_t)z * nrows * ncols;
  int c0 = blockIdx.x * 32, r0 = blockIdx.y * 32;
  int tx = threadIdx.x, ty = threadIdx.y;
  #pragma unroll
  for (int i = ty; i < 32; i += 8)
    t[i][tx] = src[(size_t)(r0 + i) * ncols + c0 + tx];
  __syncthreads();
  #pragma unroll
  for (int j = ty; j < 32; j += 8) {
    float v = t[tx][j];
    size_t o = (size_t)(c0 + j) * nrows + r0 + tx;
    __nv_bfloat16 h = __float2bfloat16(v);
    hi[o] = h;
    lo[o] = __float2bfloat16(v - __bfloat162float(h));
  }
}

__global__ void k_bias(const float* __restrict__ mb) {
  int d = threadIdx.x;
  float s = 0.f;
  #pragma unroll
  for (int r = 0; r < RR; ++r) s += mb[r * DD + d];
  g_bias_sum[d] = s;
}

// WsumT[e][d] = sum_r msg_W[r][e][d]  (fully coalesced)
__global__ void k_wsumT(const float* __restrict__ W) {
  int idx = blockIdx.x * blockDim.x + threadIdx.x;   // e*DD + d
  float s = 0.f;
  #pragma unroll
  for (int r = 0; r < RR; ++r) s += W[(size_t)r * DD * DD + idx];
  g_WsumT[idx] = s;
}

// Partial row-sums of src[b][j][d] over j (64-row segments)
__global__ void k_sum1(const float* __restrict__ src) {
  int b = blockIdx.x, seg = blockIdx.y, d = threadIdx.x;
  const float* hp = src + (size_t)b * NN * DD + (size_t)seg * 64 * DD + d;
  float s = 0.f;
  #pragma unroll 8
  for (int i = 0; i < 64; ++i) s += hp[(size_t)i * DD];
  g_msum[(size_t)(b * 8 + seg) * DD + d] = s;
}
__global__ void k_sum2(float* __restrict__ dst, float scale) {
  int b = blockIdx.x, d = threadIdx.x;
  float s = 0.f;
  #pragma unroll
  for (int seg = 0; seg < 8; ++seg) s += g_msum[(size_t)(b * 8 + seg) * DD + d];
  dst[b * DD + d] = s * scale;
}

// T[b][e] = 0.5 * sum_d hsum[b][d] * WsumT[e][d]   (fp32 exact DC correction)
__global__ void k_tgemm() {
  int idx = blockIdx.x * blockDim.x + threadIdx.x;   // b*DD + e
  int b = idx >> 9, e = idx & (DD - 1);
  const float4* hs = (const float4*)(g_hsum + (size_t)b * DD);
  const float4* ws = (const float4*)(g_WsumT + (size_t)e * DD);
  float s = 0.f;
  #pragma unroll 4
  for (int i = 0; i < DD / 4; ++i) {
    float4 a = hs[i], w = ws[i];
    s += a.x * w.x + a.y * w.y + a.z * w.z + a.w * w.w;
  }
  g_T[idx] = 0.5f * s;
}

__global__ void k_gru(const float* __restrict__ nodes, int step) {
  int idx = blockIdx.x * blockDim.x + threadIdx.x;
  const float* hsrc = (step == 0) ? nodes : g_h;
  int d = idx & (DD - 1);
  int row = idx >> 9;
  const float* gi = g_gi + (size_t)row * TD;
  const float* gh = g_gh + (size_t)row * TD;
  float ir = gi[d],        hr = gh[d];
  float iz = gi[DD + d],   hz = gh[DD + d];
  float in_ = gi[2*DD + d], hn = gh[2*DD + d];
  float r = 1.f / (1.f + __expf(-(ir + hr)));
  float z = 1.f / (1.f + __expf(-(iz + hz)));
  float targ = in_ + r * hn;
  float n = 1.f - 2.f / (1.f + __expf(2.f * targ));   // tanh
  float h = hsrc[idx];
  float hnew = (1.f - z) * n + z * h;
  g_h[idx] = hnew;
  __nv_bfloat16 hh = __float2bfloat16(hnew);
  g_hhi[idx] = hh;
  g_hlo[idx] = __float2bfloat16(hnew - __bfloat162float(hh));
}

// ---------------------------------------------------------------------------
extern "C" void kernel_launch(void* const* d_in, const int* in_sizes, int n_in,
                              void* d_out, int out_size) {
  const float* nodes = (const float*)d_in[0];
  const float* edges = (const float*)d_in[1];
  const float* msg_W = (const float*)d_in[2];
  const float* msg_b = (const float*)d_in[3];
  const float* w_ih  = (const float*)d_in[4];
  const float* w_hh  = (const float*)d_in[5];
  const float* b_ih  = (const float*)d_in[6];
  const float* b_hh  = (const float*)d_in[7];
  float* out = (float*)d_out;

  cudaFuncSetAttribute(k_hw_t,    cudaFuncAttributeMaxDynamicSharedMemorySize, 3*37888);
  cudaFuncSetAttribute(k_agg_t,   cudaFuncAttributeMaxDynamicSharedMemorySize, 4*27648);
  cudaFuncSetAttribute(k_gates_t, cudaFuncAttributeMaxDynamicSharedMemorySize, 3*37888);

  __nv_bfloat162 *hhi2, *hlo2, *ehi2;
  __nv_bfloat16 *wthi, *wtlo, *ihthi, *ihtlo, *hhthi, *hhtlo;
  float *hsum_p;
  cudaGetSymbolAddress((void**)&hhi2,  g_hhi);    cudaGetSymbolAddress((void**)&hlo2,  g_hlo);
  cudaGetSymbolAddress((void**)&ehi2,  g_ehi);
  cudaGetSymbolAddress((void**)&wthi,  g_WThi);   cudaGetSymbolAddress((void**)&wtlo,  g_WTlo);
  cudaGetSymbolAddress((void**)&ihthi, g_wihThi); cudaGetSymbolAddress((void**)&ihtlo, g_wihTlo);
  cudaGetSymbolAddress((void**)&hhthi, g_whhThi); cudaGetSymbolAddress((void**)&hhtlo, g_whhTlo);
  cudaGetSymbolAddress((void**)&hsum_p, g_hsum);

  int n4;
  n4 = BB*NN*DD/4;    k_split<<<n4/256, 256>>>((const float4*)nodes, hhi2, hlo2, n4);
  n4 = BB*RR*NN*NN/4; k_split_delta<<<n4/256, 256>>>((const float4*)edges, ehi2, n4);
  k_tsplit<<<dim3(16, 16, 8), dim3(32, 8)>>>(msg_W, wthi, wtlo, DD, DD);
  k_tsplit<<<dim3(16, 48, 1), dim3(32, 8)>>>(w_ih, ihthi, ihtlo, TD, DD);
  k_tsplit<<<dim3(16, 48, 1), dim3(32, 8)>>>(w_hh, hhthi, hhtlo, TD, DD);
  k_wsumT<<<DD*DD/256, 256>>>(msg_W);
  k_bias<<<1, DD>>>(msg_b);

  for (int s = 0; s < 2; ++s) {
    const float* hsrc = (s == 0) ? nodes : (const float*)nullptr;
    // hsum of current h (nodes at step 0, g_h afterwards)
    if (s == 0) k_sum1<<<dim3(BB, 8), DD>>>(nodes);
    else {
      float* hp; cudaGetSymbolAddress((void**)&hp, g_h);
      k_sum1<<<dim3(BB, 8), DD>>>(hp);
    }
    k_sum2<<<BB, DD>>>(hsum_p, 1.0f);
    k_tgemm<<<BB*DD/256, 256>>>();
    k_hw_t   <<<dim3(64, 4, 8),  256, 3*37888>>>();
    k_agg_t  <<<dim3(4, 4, 16),  256, 4*27648>>>();
    k_gates_t<<<dim3(64, 12, 2), 256, 3*37888>>>(b_ih, b_hh);
    k_gru    <<<(BB*NN*DD)/256, 256>>>(nodes, s);
    (void)hsrc;
  }
  {
    float* hp; cudaGetSymbolAddress((void**)&hp, g_h);
    k_sum1<<<dim3(BB, 8), DD>>>(hp);
  }
  k_sum2<<<BB, DD>>>(out, 1.0f / NN);
}